// round 1
// baseline (speedup 1.0000x reference)
#include <cuda_runtime.h>
#include <cuda_bf16.h>
#include <cstdint>

#define NNODE 100000
#define DDIM  256
#define EMAX  3400000

// ---------------- scratch (static device globals; no allocation) -------------
__device__ float g_h2  [(size_t)NNODE * DDIM];   // h @ W for current layer
__device__ float g_hmid[(size_t)NNODE * DDIM];   // output of layer 1
__device__ float g_ssrc[NNODE];
__device__ float g_sdst[NNODE];
__device__ int   g_counts[NNODE];
__device__ int   g_rowptr[NNODE + 1];
__device__ int   g_cursor[NNODE];
__device__ int   g_col[EMAX];

// ---------------- CSR build --------------------------------------------------
__global__ void zero_counts_k(int n) {
    int i = blockIdx.x * blockDim.x + threadIdx.x;
    if (i < n) g_counts[i] = 0;
}

__global__ void hist_k(const int* __restrict__ src, int E) {
    int i = blockIdx.x * blockDim.x + threadIdx.x;
    if (i < E) atomicAdd(&g_counts[src[i]], 1);
}

// single-block exclusive scan over g_counts -> g_rowptr (+ cursor copy)
__global__ void scan_k(int n) {
    __shared__ int sh[1024];
    __shared__ int carry;
    if (threadIdx.x == 0) carry = 0;
    __syncthreads();
    for (int base = 0; base < n; base += 1024) {
        int i = base + threadIdx.x;
        int v = (i < n) ? g_counts[i] : 0;
        sh[threadIdx.x] = v;
        __syncthreads();
        #pragma unroll
        for (int off = 1; off < 1024; off <<= 1) {
            int t = (threadIdx.x >= off) ? sh[threadIdx.x - off] : 0;
            __syncthreads();
            sh[threadIdx.x] += t;
            __syncthreads();
        }
        int excl = carry + sh[threadIdx.x] - v;
        if (i < n) { g_rowptr[i] = excl; g_cursor[i] = excl; }
        __syncthreads();
        if (threadIdx.x == 1023) carry += sh[1023];
        __syncthreads();
    }
    if (threadIdx.x == 0) g_rowptr[n] = carry;
}

__global__ void scatter_k(const int* __restrict__ src, const int* __restrict__ dst, int E) {
    int i = blockIdx.x * blockDim.x + threadIdx.x;
    if (i < E) {
        int s = src[i];
        int p = atomicAdd(&g_cursor[s], 1);
        g_col[p] = dst[i];
    }
}

// ---------------- SGEMM: C[M,256] = A[M,256] @ B[256,256] --------------------
// BM=128, BN=64, BK=16; 256 threads; thread tile 8x4.
__global__ __launch_bounds__(256) void sgemm_k(const float* __restrict__ A,
                                               const float* __restrict__ B,
                                               float* __restrict__ C, int M) {
    __shared__ float As[16][128];
    __shared__ float Bs[16][64];
    const int tid = threadIdx.x;
    const int rowBlock = blockIdx.x * 128;
    const int colBlock = blockIdx.y * 64;
    const int tx = tid & 15;   // 4 cols each
    const int ty = tid >> 4;   // 8 rows each

    float acc[8][4];
    #pragma unroll
    for (int i = 0; i < 8; i++)
        #pragma unroll
        for (int j = 0; j < 4; j++) acc[i][j] = 0.f;

    for (int k0 = 0; k0 < 256; k0 += 16) {
        // A tile: 128 rows x 16 cols = 512 float4; 2 per thread (transpose into As)
        #pragma unroll
        for (int l = 0; l < 2; l++) {
            int q = tid * 2 + l;
            int r = q >> 2, kq = q & 3;
            int grow = rowBlock + r;
            float4 v = (grow < M)
                ? ((const float4*)(A + (size_t)grow * 256 + k0))[kq]
                : make_float4(0.f, 0.f, 0.f, 0.f);
            As[kq * 4 + 0][r] = v.x;
            As[kq * 4 + 1][r] = v.y;
            As[kq * 4 + 2][r] = v.z;
            As[kq * 4 + 3][r] = v.w;
        }
        // B tile: 16 rows x 64 cols = 256 float4; 1 per thread
        {
            int r = tid >> 4, cq = tid & 15;
            float4 v = ((const float4*)(B + (size_t)(k0 + r) * 256 + colBlock))[cq];
            ((float4*)&Bs[r][0])[cq] = v;
        }
        __syncthreads();
        #pragma unroll
        for (int k = 0; k < 16; k++) {
            float4 a0 = *(const float4*)&As[k][ty * 8];
            float4 a1 = *(const float4*)&As[k][ty * 8 + 4];
            float4 b0 = *(const float4*)&Bs[k][tx * 4];
            float av[8] = {a0.x, a0.y, a0.z, a0.w, a1.x, a1.y, a1.z, a1.w};
            float bv[4] = {b0.x, b0.y, b0.z, b0.w};
            #pragma unroll
            for (int i = 0; i < 8; i++)
                #pragma unroll
                for (int j = 0; j < 4; j++) acc[i][j] += av[i] * bv[j];
        }
        __syncthreads();
    }
    #pragma unroll
    for (int i = 0; i < 8; i++) {
        int grow = rowBlock + ty * 8 + i;
        if (grow < M) {
            float4 v = make_float4(acc[i][0], acc[i][1], acc[i][2], acc[i][3]);
            ((float4*)(C + (size_t)grow * 256 + colBlock))[tx] = v;
        }
    }
}

// ---------------- score projections: s_src = h2@a[:256], s_dst = h2@a[256:] --
__global__ void sdot_k(const float* __restrict__ h2, const float* __restrict__ a, int n) {
    int warp = (blockIdx.x * blockDim.x + threadIdx.x) >> 5;
    int lane = threadIdx.x & 31;
    if (warp >= n) return;
    const float4* row = (const float4*)(h2 + (size_t)warp * 256);
    const float4* a1  = (const float4*)a;
    const float4* a2  = (const float4*)(a + 256);
    float s1 = 0.f, s2 = 0.f;
    #pragma unroll
    for (int t = 0; t < 2; t++) {
        float4 v  = row[lane * 2 + t];
        float4 w1 = a1 [lane * 2 + t];
        float4 w2 = a2 [lane * 2 + t];
        s1 += v.x * w1.x + v.y * w1.y + v.z * w1.z + v.w * w1.w;
        s2 += v.x * w2.x + v.y * w2.y + v.z * w2.z + v.w * w2.w;
    }
    #pragma unroll
    for (int off = 16; off; off >>= 1) {
        s1 += __shfl_xor_sync(0xffffffffu, s1, off);
        s2 += __shfl_xor_sync(0xffffffffu, s2, off);
    }
    if (lane == 0) { g_ssrc[warp] = s1; g_sdst[warp] = s2; }
}

// ---------------- edge aggregation: one warp per node ------------------------
__device__ __forceinline__ float elu1(float x) {
    return x > 0.f ? x : (__expf(x) - 1.f);
}

__global__ __launch_bounds__(256) void agg_k(const float* __restrict__ h2,
                                             float* __restrict__ out, int n) {
    int warp = (blockIdx.x * blockDim.x + threadIdx.x) >> 5;
    int lane = threadIdx.x & 31;
    if (warp >= n) return;
    const int start = g_rowptr[warp];
    const int end   = g_rowptr[warp + 1];
    const float s_i = g_ssrc[warp];

    float4 acc0 = make_float4(0.f, 0.f, 0.f, 0.f);
    float4 acc1 = make_float4(0.f, 0.f, 0.f, 0.f);
    float denom = 0.f;

    for (int j = start; j < end; j += 32) {
        int myj = j + lane;
        float e = 0.f;
        int d = 0;
        if (myj < end) {
            d = g_col[myj];
            float sc = s_i + g_sdst[d];
            float l  = sc > 0.f ? sc : 0.2f * sc;   // leaky_relu(0.2)
            e = __expf(-l);
        }
        int cnt = end - j;
        if (cnt > 32) cnt = 32;
        #pragma unroll 4
        for (int k = 0; k < cnt; k++) {
            float ek = __shfl_sync(0xffffffffu, e, k);
            int   dk = __shfl_sync(0xffffffffu, d, k);
            const float4* row = (const float4*)(h2 + (size_t)dk * 256);
            float4 v0 = row[lane * 2];
            float4 v1 = row[lane * 2 + 1];
            acc0.x += ek * v0.x; acc0.y += ek * v0.y;
            acc0.z += ek * v0.z; acc0.w += ek * v0.w;
            acc1.x += ek * v1.x; acc1.y += ek * v1.y;
            acc1.z += ek * v1.z; acc1.w += ek * v1.w;
            denom += ek;
        }
    }
    float inv = denom > 0.f ? 1.0f / denom : 0.f;
    float4 o0, o1;
    o0.x = elu1(acc0.x * inv); o0.y = elu1(acc0.y * inv);
    o0.z = elu1(acc0.z * inv); o0.w = elu1(acc0.w * inv);
    o1.x = elu1(acc1.x * inv); o1.y = elu1(acc1.y * inv);
    o1.z = elu1(acc1.z * inv); o1.w = elu1(acc1.w * inv);
    float4* orow = (float4*)(out + (size_t)warp * 256);
    orow[lane * 2]     = o0;
    orow[lane * 2 + 1] = o1;
}

// ---------------- launch -----------------------------------------------------
extern "C" void kernel_launch(void* const* d_in, const int* in_sizes, int n_in,
                              void* d_out, int out_size) {
    const float* emb  = (const float*)d_in[0];
    const float* W1   = (const float*)d_in[1];
    const float* a1   = (const float*)d_in[2];
    const float* W2   = (const float*)d_in[3];
    const float* a2   = (const float*)d_in[4];
    const int*   edges = (const int*)d_in[5];

    const int N = in_sizes[0] / DDIM;     // 100000
    const int E = in_sizes[5] / 2;        // 3300000
    const int* src = edges;
    const int* dst = edges + E;

    float* h2;   cudaGetSymbolAddress((void**)&h2,   g_h2);
    float* hmid; cudaGetSymbolAddress((void**)&hmid, g_hmid);
    float* out  = (float*)d_out;

    const int TB = 256;
    dim3 gemm_grid((N + 127) / 128, 4);

    // CSR build (identical both layers)
    zero_counts_k<<<(N + TB - 1) / TB, TB>>>(N);
    hist_k<<<(E + TB - 1) / TB, TB>>>(src, E);
    scan_k<<<1, 1024>>>(N);
    scatter_k<<<(E + TB - 1) / TB, TB>>>(src, dst, E);

    // layer 1
    sgemm_k<<<gemm_grid, TB>>>(emb, W1, h2, N);
    sdot_k<<<(N * 32 + TB - 1) / TB, TB>>>(h2, a1, N);
    agg_k<<<(N * 32 + TB - 1) / TB, TB>>>(h2, hmid, N);

    // layer 2
    sgemm_k<<<gemm_grid, TB>>>(hmid, W2, h2, N);
    sdot_k<<<(N * 32 + TB - 1) / TB, TB>>>(h2, a2, N);
    agg_k<<<(N * 32 + TB - 1) / TB, TB>>>(h2, out, N);
}

// round 4
// speedup vs baseline: 1.2788x; 1.2788x over previous
#include <cuda_runtime.h>
#include <cuda_fp16.h>
#include <cuda_bf16.h>
#include <cstdint>

#define NNODE 100000
#define DDIM  256
#define EMAX  3400000

// ---------------- scratch (static device globals; no allocation) -------------
__device__ float  g_h2  [(size_t)NNODE * DDIM];   // h @ W (fp32, for sdot)
__device__ __half g_h2h [(size_t)NNODE * DDIM];   // h @ W (fp16, for gather)
__device__ float  g_hmid[(size_t)NNODE * DDIM];   // output of layer 1
__device__ float  g_ssrc[NNODE];
__device__ float  g_sdst[NNODE];
__device__ int    g_counts[NNODE];
__device__ int    g_rowptr[NNODE + 1];
__device__ int    g_cursor[NNODE];
__device__ int    g_col[EMAX];

// ---------------- CSR build --------------------------------------------------
__global__ void zero_counts_k(int n) {
    int i = blockIdx.x * blockDim.x + threadIdx.x;
    if (i < n) g_counts[i] = 0;
}

__global__ void hist_k(const int* __restrict__ src, int E) {
    int i = blockIdx.x * blockDim.x + threadIdx.x;
    if (i < E) atomicAdd(&g_counts[src[i]], 1);
}

// single-block exclusive scan (shfl-based, 4 elems/thread/iter)
__global__ void scan_k(int n) {
    __shared__ int wsum[32];
    __shared__ int carry;
    const int tid = threadIdx.x, lane = tid & 31, w = tid >> 5;
    if (tid == 0) carry = 0;
    __syncthreads();
    for (int base = 0; base < n; base += 4096) {
        int i0 = base + tid * 4;
        int v0 = 0, v1 = 0, v2 = 0, v3 = 0;
        if (i0 + 3 < n) {
            int4 t = *(const int4*)&g_counts[i0];
            v0 = t.x; v1 = t.y; v2 = t.z; v3 = t.w;
        } else {
            if (i0 + 0 < n) v0 = g_counts[i0 + 0];
            if (i0 + 1 < n) v1 = g_counts[i0 + 1];
            if (i0 + 2 < n) v2 = g_counts[i0 + 2];
            if (i0 + 3 < n) v3 = g_counts[i0 + 3];
        }
        int s0 = v0, s1 = s0 + v1, s2 = s1 + v2, s3 = s2 + v3;
        int incl = s3;
        #pragma unroll
        for (int off = 1; off < 32; off <<= 1) {
            int u = __shfl_up_sync(0xffffffffu, incl, off);
            if (lane >= off) incl += u;
        }
        if (lane == 31) wsum[w] = incl;
        __syncthreads();
        if (w == 0) {
            int x = wsum[lane], xi = x;
            #pragma unroll
            for (int off = 1; off < 32; off <<= 1) {
                int u = __shfl_up_sync(0xffffffffu, xi, off);
                if (lane >= off) xi += u;
            }
            wsum[lane] = xi - x;   // exclusive warp offset
        }
        __syncthreads();
        int eb = carry + wsum[w] + (incl - s3);
        if (i0 + 0 < n) { g_rowptr[i0 + 0] = eb;      g_cursor[i0 + 0] = eb;      }
        if (i0 + 1 < n) { g_rowptr[i0 + 1] = eb + s0; g_cursor[i0 + 1] = eb + s0; }
        if (i0 + 2 < n) { g_rowptr[i0 + 2] = eb + s1; g_cursor[i0 + 2] = eb + s1; }
        if (i0 + 3 < n) { g_rowptr[i0 + 3] = eb + s2; g_cursor[i0 + 3] = eb + s2; }
        __syncthreads();
        if (tid == 1023) carry += wsum[31] + incl;
        __syncthreads();
    }
    if (tid == 0) g_rowptr[n] = carry;
}

__global__ void scatter_k(const int* __restrict__ src, const int* __restrict__ dst, int E) {
    int i = blockIdx.x * blockDim.x + threadIdx.x;
    if (i < E) {
        int s = src[i];
        int p = atomicAdd(&g_cursor[s], 1);
        g_col[p] = dst[i];
    }
}

// ---------------- SGEMM: C[M,256] = A[M,256] @ B[256,256] --------------------
// BM=128, BN=128, BK=16; 256 threads; 8x8 micro-tile; fused fp16 epilogue.
__global__ __launch_bounds__(256) void sgemm_k(const float* __restrict__ A,
                                               const float* __restrict__ B,
                                               float* __restrict__ C,
                                               __half* __restrict__ Ch, int M) {
    __shared__ float As[16][128];
    __shared__ float Bs[16][128];
    const int tid = threadIdx.x;
    const int rowBlock = blockIdx.x * 128;
    const int colBlock = blockIdx.y * 128;
    const int tx = tid & 15;   // 8 cols each
    const int ty = tid >> 4;   // 8 rows each

    float acc[8][8];
    #pragma unroll
    for (int i = 0; i < 8; i++)
        #pragma unroll
        for (int j = 0; j < 8; j++) acc[i][j] = 0.f;

    for (int k0 = 0; k0 < 256; k0 += 16) {
        // A tile: 128 rows x 16 k = 512 float4; 2 per thread (transposed)
        #pragma unroll
        for (int l = 0; l < 2; l++) {
            int q = tid * 2 + l;
            int r = q >> 2, kq = q & 3;
            int grow = rowBlock + r;
            float4 v = (grow < M)
                ? ((const float4*)(A + (size_t)grow * 256 + k0))[kq]
                : make_float4(0.f, 0.f, 0.f, 0.f);
            As[kq * 4 + 0][r] = v.x;
            As[kq * 4 + 1][r] = v.y;
            As[kq * 4 + 2][r] = v.z;
            As[kq * 4 + 3][r] = v.w;
        }
        // B tile: 16 k x 128 cols = 512 float4; 2 per thread
        #pragma unroll
        for (int l = 0; l < 2; l++) {
            int q = tid * 2 + l;
            int r = q >> 5, cq = q & 31;
            float4 v = ((const float4*)(B + (size_t)(k0 + r) * 256 + colBlock))[cq];
            ((float4*)&Bs[r][0])[cq] = v;
        }
        __syncthreads();
        #pragma unroll
        for (int k = 0; k < 16; k++) {
            float a[8], b[8];
            *(float4*)&a[0] = *(const float4*)&As[k][ty * 8];
            *(float4*)&a[4] = *(const float4*)&As[k][ty * 8 + 4];
            *(float4*)&b[0] = *(const float4*)&Bs[k][tx * 8];
            *(float4*)&b[4] = *(const float4*)&Bs[k][tx * 8 + 4];
            #pragma unroll
            for (int i = 0; i < 8; i++)
                #pragma unroll
                for (int j = 0; j < 8; j++) acc[i][j] += a[i] * b[j];
        }
        __syncthreads();
    }
    #pragma unroll
    for (int i = 0; i < 8; i++) {
        int grow = rowBlock + ty * 8 + i;
        if (grow >= M) continue;
        float4* crow = (float4*)(C + (size_t)grow * 256 + colBlock);
        crow[tx * 2]     = *(float4*)&acc[i][0];
        crow[tx * 2 + 1] = *(float4*)&acc[i][4];
        __half2 p0 = __floats2half2_rn(acc[i][0], acc[i][1]);
        __half2 p1 = __floats2half2_rn(acc[i][2], acc[i][3]);
        __half2 p2 = __floats2half2_rn(acc[i][4], acc[i][5]);
        __half2 p3 = __floats2half2_rn(acc[i][6], acc[i][7]);
        uint4 hv;
        hv.x = *(unsigned int*)&p0; hv.y = *(unsigned int*)&p1;
        hv.z = *(unsigned int*)&p2; hv.w = *(unsigned int*)&p3;
        ((uint4*)(Ch + (size_t)grow * 256 + colBlock))[tx] = hv;
    }
}

// ---------------- score projections ------------------------------------------
__global__ void sdot_k(const float* __restrict__ h2, const float* __restrict__ a, int n) {
    int warp = (blockIdx.x * blockDim.x + threadIdx.x) >> 5;
    int lane = threadIdx.x & 31;
    if (warp >= n) return;
    const float4* row = (const float4*)(h2 + (size_t)warp * 256);
    const float4* a1  = (const float4*)a;
    const float4* a2  = (const float4*)(a + 256);
    float s1 = 0.f, s2 = 0.f;
    #pragma unroll
    for (int t = 0; t < 2; t++) {
        float4 v  = row[lane * 2 + t];
        float4 w1 = a1 [lane * 2 + t];
        float4 w2 = a2 [lane * 2 + t];
        s1 += v.x * w1.x + v.y * w1.y + v.z * w1.z + v.w * w1.w;
        s2 += v.x * w2.x + v.y * w2.y + v.z * w2.z + v.w * w2.w;
    }
    #pragma unroll
    for (int off = 16; off; off >>= 1) {
        s1 += __shfl_xor_sync(0xffffffffu, s1, off);
        s2 += __shfl_xor_sync(0xffffffffu, s2, off);
    }
    if (lane == 0) { g_ssrc[warp] = s1; g_sdst[warp] = s2; }
}

// ---------------- edge aggregation: one warp per node, fp16 gather -----------
__device__ __forceinline__ float elu1(float x) {
    return x > 0.f ? x : (__expf(x) - 1.f);
}

__global__ __launch_bounds__(256) void agg_k(const __half* __restrict__ h2h,
                                             float* __restrict__ out, int n) {
    int warp = (blockIdx.x * blockDim.x + threadIdx.x) >> 5;
    int lane = threadIdx.x & 31;
    if (warp >= n) return;
    const int start = g_rowptr[warp];
    const int end   = g_rowptr[warp + 1];
    const float s_i = g_ssrc[warp];

    float acc[8];
    #pragma unroll
    for (int t = 0; t < 8; t++) acc[t] = 0.f;
    float denom = 0.f;

    for (int j = start; j < end; j += 32) {
        int myj = j + lane;
        float e = 0.f;
        int d = 0;
        if (myj < end) {
            d = g_col[myj];
            float sc = s_i + g_sdst[d];
            float l  = sc > 0.f ? sc : 0.2f * sc;   // leaky_relu(0.2)
            e = __expf(-l);
        }
        int cnt = end - j;
        if (cnt > 32) cnt = 32;
        #pragma unroll 4
        for (int k = 0; k < cnt; k++) {
            float ek = __shfl_sync(0xffffffffu, e, k);
            int   dk = __shfl_sync(0xffffffffu, d, k);
            uint4 v = ((const uint4*)(h2h + (size_t)dk * 256))[lane];
            __half2 p0 = *(__half2*)&v.x;
            __half2 p1 = *(__half2*)&v.y;
            __half2 p2 = *(__half2*)&v.z;
            __half2 p3 = *(__half2*)&v.w;
            float2 f0 = __half22float2(p0);
            float2 f1 = __half22float2(p1);
            float2 f2 = __half22float2(p2);
            float2 f3 = __half22float2(p3);
            acc[0] += ek * f0.x; acc[1] += ek * f0.y;
            acc[2] += ek * f1.x; acc[3] += ek * f1.y;
            acc[4] += ek * f2.x; acc[5] += ek * f2.y;
            acc[6] += ek * f3.x; acc[7] += ek * f3.y;
            denom += ek;
        }
    }
    float inv = denom > 0.f ? 1.0f / denom : 0.f;
    float o[8];
    #pragma unroll
    for (int t = 0; t < 8; t++) o[t] = elu1(acc[t] * inv);
    float4* orow = (float4*)(out + (size_t)warp * 256 + lane * 8);
    orow[0] = *(float4*)&o[0];
    orow[1] = *(float4*)&o[4];
}

// ---------------- launch -----------------------------------------------------
extern "C" void kernel_launch(void* const* d_in, const int* in_sizes, int n_in,
                              void* d_out, int out_size) {
    const float* emb  = (const float*)d_in[0];
    const float* W1   = (const float*)d_in[1];
    const float* a1   = (const float*)d_in[2];
    const float* W2   = (const float*)d_in[3];
    const float* a2   = (const float*)d_in[4];
    const int*   edges = (const int*)d_in[5];

    const int N = in_sizes[0] / DDIM;     // 100000
    const int E = in_sizes[5] / 2;        // 3300000
    const int* src = edges;
    const int* dst = edges + E;

    float*  h2;   cudaGetSymbolAddress((void**)&h2,   g_h2);
    __half* h2h;  cudaGetSymbolAddress((void**)&h2h,  g_h2h);
    float*  hmid; cudaGetSymbolAddress((void**)&hmid, g_hmid);
    float*  out  = (float*)d_out;

    const int TB = 256;
    dim3 gemm_grid((N + 127) / 128, 2);

    // CSR build
    zero_counts_k<<<(N + TB - 1) / TB, TB>>>(N);
    hist_k<<<(E + TB - 1) / TB, TB>>>(src, E);
    scan_k<<<1, 1024>>>(N);
    scatter_k<<<(E + TB - 1) / TB, TB>>>(src, dst, E);

    // layer 1
    sgemm_k<<<gemm_grid, TB>>>(emb, W1, h2, h2h, N);
    sdot_k<<<(N * 32 + TB - 1) / TB, TB>>>(h2, a1, N);
    agg_k<<<(N * 32 + TB - 1) / TB, TB>>>(h2h, hmid, N);

    // layer 2
    sgemm_k<<<gemm_grid, TB>>>(hmid, W2, h2, h2h, N);
    sdot_k<<<(N * 32 + TB - 1) / TB, TB>>>(h2, a2, N);
    agg_k<<<(N * 32 + TB - 1) / TB, TB>>>(h2h, out, N);
}

// round 6
// speedup vs baseline: 1.8804x; 1.4705x over previous
#include <cuda_runtime.h>
#include <cuda_fp16.h>
#include <cuda_bf16.h>
#include <cstdint>

#define NNODE 100000
#define DDIM  256
#define EMAX  3400000

// ---------------- scratch (static device globals; no allocation) -------------
__device__ __half g_h2h [(size_t)NNODE * DDIM];   // h @ W (fp16, for gather)
__device__ float  g_hmid[(size_t)NNODE * DDIM];   // output of layer 1
__device__ float  g_ssrc[NNODE];
__device__ float  g_sdst[NNODE];
__device__ int    g_counts[NNODE];
__device__ int    g_rowptr[NNODE + 1];
__device__ int    g_cursor[NNODE];
__device__ int    g_col[EMAX];
// W^T split into bf16 hi/lo, per layer: [N=256][K=256]
__device__ __nv_bfloat16 g_W1h[65536], g_W1l[65536];
__device__ __nv_bfloat16 g_W2h[65536], g_W2l[65536];

// ---------------- CSR build --------------------------------------------------
__global__ void zero_counts_k(int n) {
    int i = blockIdx.x * blockDim.x + threadIdx.x;
    if (i < n) g_counts[i] = 0;
}

__global__ void zero_s_k(int n) {
    int i = blockIdx.x * blockDim.x + threadIdx.x;
    if (i < n) { g_ssrc[i] = 0.f; g_sdst[i] = 0.f; }
}

__global__ void hist_k(const int* __restrict__ src, int E) {
    int i = blockIdx.x * blockDim.x + threadIdx.x;
    if (i < E) atomicAdd(&g_counts[src[i]], 1);
}

__global__ void scan_k(int n) {
    __shared__ int wsum[32];
    __shared__ int carry;
    const int tid = threadIdx.x, lane = tid & 31, w = tid >> 5;
    if (tid == 0) carry = 0;
    __syncthreads();
    for (int base = 0; base < n; base += 4096) {
        int i0 = base + tid * 4;
        int v0 = 0, v1 = 0, v2 = 0, v3 = 0;
        if (i0 + 3 < n) {
            int4 t = *(const int4*)&g_counts[i0];
            v0 = t.x; v1 = t.y; v2 = t.z; v3 = t.w;
        } else {
            if (i0 + 0 < n) v0 = g_counts[i0 + 0];
            if (i0 + 1 < n) v1 = g_counts[i0 + 1];
            if (i0 + 2 < n) v2 = g_counts[i0 + 2];
            if (i0 + 3 < n) v3 = g_counts[i0 + 3];
        }
        int s0 = v0, s1 = s0 + v1, s2 = s1 + v2, s3 = s2 + v3;
        int incl = s3;
        #pragma unroll
        for (int off = 1; off < 32; off <<= 1) {
            int u = __shfl_up_sync(0xffffffffu, incl, off);
            if (lane >= off) incl += u;
        }
        if (lane == 31) wsum[w] = incl;
        __syncthreads();
        if (w == 0) {
            int x = wsum[lane], xi = x;
            #pragma unroll
            for (int off = 1; off < 32; off <<= 1) {
                int u = __shfl_up_sync(0xffffffffu, xi, off);
                if (lane >= off) xi += u;
            }
            wsum[lane] = xi - x;
        }
        __syncthreads();
        int eb = carry + wsum[w] + (incl - s3);
        if (i0 + 0 < n) { g_rowptr[i0 + 0] = eb;      g_cursor[i0 + 0] = eb;      }
        if (i0 + 1 < n) { g_rowptr[i0 + 1] = eb + s0; g_cursor[i0 + 1] = eb + s0; }
        if (i0 + 2 < n) { g_rowptr[i0 + 2] = eb + s1; g_cursor[i0 + 2] = eb + s1; }
        if (i0 + 3 < n) { g_rowptr[i0 + 3] = eb + s2; g_cursor[i0 + 3] = eb + s2; }
        __syncthreads();
        if (tid == 1023) carry += wsum[31] + incl;
        __syncthreads();
    }
    if (tid == 0) g_rowptr[n] = carry;
}

__global__ void scatter_k(const int* __restrict__ src, const int* __restrict__ dst, int E) {
    int i = blockIdx.x * blockDim.x + threadIdx.x;
    if (i < E) {
        int s = src[i];
        int p = atomicAdd(&g_cursor[s], 1);
        g_col[p] = dst[i];
    }
}

// ---------------- W transpose + bf16 hi/lo split ------------------------------
__global__ void wsplit_k(const float* __restrict__ W,
                         __nv_bfloat16* __restrict__ Wh,
                         __nv_bfloat16* __restrict__ Wl) {
    int n = blockIdx.x, k = threadIdx.x;
    float v = W[k * 256 + n];
    __nv_bfloat16 h = __float2bfloat16_rn(v);
    Wh[n * 256 + k] = h;
    Wl[n * 256 + k] = __float2bfloat16_rn(v - __bfloat162float(h));
}

// ---------------- HMMA split-precision GEMM ----------------------------------
// C[M,256] = A[M,256] @ W ; D = Ah*Bh + Ah*Bl + Al*Bh (bf16 hi/lo, fp32 acc).
// CTA = 128 rows x 128 cols (grid.y=2 for N=256), 8 warps (2m x 4n),
// warp tile 64x32, mma.sync.m16n8k16. K chunk 32, double-buffered smem.
// Epilogue: writes fp16 h2 shadow + fused a-projections via atomics.
#define ROWSTRIDE 80              // bytes per 32-elem bf16 row (conflict-free)
#define TILE_B    (128 * ROWSTRIDE)   // 10240
#define STAGE_B   (4 * TILE_B)        // Ah|Al|Bh|Bl = 40960
#define GSMEM_B   (2 * STAGE_B)       // 81920

__device__ __forceinline__ void mma_bf16(float* c, uint32_t a0, uint32_t a1,
                                         uint32_t a2, uint32_t a3,
                                         uint32_t b0, uint32_t b1) {
    asm volatile(
        "mma.sync.aligned.m16n8k16.row.col.f32.bf16.bf16.f32 "
        "{%0,%1,%2,%3}, {%4,%5,%6,%7}, {%8,%9}, {%0,%1,%2,%3};"
        : "+f"(c[0]), "+f"(c[1]), "+f"(c[2]), "+f"(c[3])
        : "r"(a0), "r"(a1), "r"(a2), "r"(a3), "r"(b0), "r"(b1));
}

__global__ __launch_bounds__(256, 1) void mmagemm_k(const float* __restrict__ A,
                                                    const __nv_bfloat16* __restrict__ Bh,
                                                    const __nv_bfloat16* __restrict__ Bl,
                                                    const float* __restrict__ avec,
                                                    __half* __restrict__ Chalf, int M) {
    extern __shared__ char smem[];
    const int tid = threadIdx.x;
    const int rowBlock = blockIdx.x * 128;
    const int nBlock   = blockIdx.y * 128;

    const int wid = tid >> 5, lane = tid & 31;
    const int warpRow = (wid >> 2) * 64;   // 0 / 64
    const int warpCol = (wid & 3) * 32;    // 0..96
    const int qrow = lane >> 2, qcol = lane & 3;

    float acc[4][4][4];
    #pragma unroll
    for (int i = 0; i < 4; i++)
        #pragma unroll
        for (int j = 0; j < 4; j++)
            #pragma unroll
            for (int t = 0; t < 4; t++) acc[i][j][t] = 0.f;

    // gmem->reg prefetch mapping (A and B share: row = tid>>1, half = tid&1)
    const int ldRow = tid >> 1, ldHalf = tid & 1;
    const int aRowG = rowBlock + ldRow;
    float fA[16];
    uint4 rBh[2], rBl[2];

    // ---- helpers as lambdas ----
    auto load_gmem = [&](int kc) {
        const int kof = kc * 32 + ldHalf * 16;
        if (aRowG < M) {
            const float4* ap = (const float4*)(A + (size_t)aRowG * 256 + kof);
            #pragma unroll
            for (int q = 0; q < 4; q++) *(float4*)&fA[q * 4] = ap[q];
        } else {
            #pragma unroll
            for (int q = 0; q < 16; q++) fA[q] = 0.f;
        }
        const size_t bgo = (size_t)(nBlock + ldRow) * 256 + kof;
        rBh[0] = ((const uint4*)(Bh + bgo))[0];
        rBh[1] = ((const uint4*)(Bh + bgo))[1];
        rBl[0] = ((const uint4*)(Bl + bgo))[0];
        rBl[1] = ((const uint4*)(Bl + bgo))[1];
    };
    auto store_smem = [&](int s) {
        char* st = smem + s * STAGE_B;
        // A: convert fp32 -> bf16 hi/lo
        uint32_t hp[8], lp[8];
        #pragma unroll
        for (int j = 0; j < 8; j++) {
            float x0 = fA[2 * j], x1 = fA[2 * j + 1];
            __nv_bfloat16 h0 = __float2bfloat16_rn(x0);
            __nv_bfloat16 h1 = __float2bfloat16_rn(x1);
            __nv_bfloat162 hpp(h0, h1);
            hp[j] = *(uint32_t*)&hpp;
            __nv_bfloat16 l0 = __float2bfloat16_rn(x0 - __bfloat162float(h0));
            __nv_bfloat16 l1 = __float2bfloat16_rn(x1 - __bfloat162float(h1));
            __nv_bfloat162 lpp(l0, l1);
            lp[j] = *(uint32_t*)&lpp;
        }
        const int off = ldRow * ROWSTRIDE + ldHalf * 32;
        *(uint4*)(st + off)               = *(uint4*)&hp[0];
        *(uint4*)(st + off + 16)          = *(uint4*)&hp[4];
        *(uint4*)(st + TILE_B + off)      = *(uint4*)&lp[0];
        *(uint4*)(st + TILE_B + off + 16) = *(uint4*)&lp[4];
        *(uint4*)(st + 2 * TILE_B + off)      = rBh[0];
        *(uint4*)(st + 2 * TILE_B + off + 16) = rBh[1];
        *(uint4*)(st + 3 * TILE_B + off)      = rBl[0];
        *(uint4*)(st + 3 * TILE_B + off + 16) = rBl[1];
    };

    load_gmem(0);
    store_smem(0);
    __syncthreads();

    for (int kc = 0; kc < 8; kc++) {
        const int cur = kc & 1;
        if (kc < 7) load_gmem(kc + 1);

        const char* sAh = smem + cur * STAGE_B;
        const char* sAl = sAh + TILE_B;
        const char* sBh = sAh + 2 * TILE_B;
        const char* sBl = sAh + 3 * TILE_B;

        #pragma unroll
        for (int ks = 0; ks < 2; ks++) {
            const int kb = ks * 32 + qcol * 4;
            uint32_t bhf[4][2], blf[4][2];
            #pragma unroll
            for (int j = 0; j < 4; j++) {
                const int off = (warpCol + j * 8 + qrow) * ROWSTRIDE + kb;
                bhf[j][0] = *(const uint32_t*)(sBh + off);
                bhf[j][1] = *(const uint32_t*)(sBh + off + 16);
                blf[j][0] = *(const uint32_t*)(sBl + off);
                blf[j][1] = *(const uint32_t*)(sBl + off + 16);
            }
            #pragma unroll
            for (int i = 0; i < 4; i++) {
                const int off = (warpRow + i * 16 + qrow) * ROWSTRIDE + kb;
                uint32_t ah0 = *(const uint32_t*)(sAh + off);
                uint32_t ah1 = *(const uint32_t*)(sAh + off + 8 * ROWSTRIDE);
                uint32_t ah2 = *(const uint32_t*)(sAh + off + 16);
                uint32_t ah3 = *(const uint32_t*)(sAh + off + 8 * ROWSTRIDE + 16);
                uint32_t al0 = *(const uint32_t*)(sAl + off);
                uint32_t al1 = *(const uint32_t*)(sAl + off + 8 * ROWSTRIDE);
                uint32_t al2 = *(const uint32_t*)(sAl + off + 16);
                uint32_t al3 = *(const uint32_t*)(sAl + off + 8 * ROWSTRIDE + 16);
                #pragma unroll
                for (int j = 0; j < 4; j++) {
                    mma_bf16(acc[i][j], ah0, ah1, ah2, ah3, bhf[j][0], bhf[j][1]);
                    mma_bf16(acc[i][j], ah0, ah1, ah2, ah3, blf[j][0], blf[j][1]);
                    mma_bf16(acc[i][j], al0, al1, al2, al3, bhf[j][0], bhf[j][1]);
                }
            }
        }
        if (kc < 7) {
            store_smem((kc + 1) & 1);
            __syncthreads();
        }
    }

    // ---- epilogue: fp16 store + fused score projections ----
    float a1x[4], a1y[4], a2x[4], a2y[4];
    #pragma unroll
    for (int j = 0; j < 4; j++) {
        const int c0 = nBlock + warpCol + j * 8 + 2 * qcol;
        float2 p1 = *(const float2*)(avec + c0);
        float2 p2 = *(const float2*)(avec + 256 + c0);
        a1x[j] = p1.x; a1y[j] = p1.y;
        a2x[j] = p2.x; a2y[j] = p2.y;
    }
    #pragma unroll
    for (int i = 0; i < 4; i++) {
        const int r0 = rowBlock + warpRow + i * 16 + qrow;
        const int r1 = r0 + 8;
        float s1_0 = 0.f, s2_0 = 0.f, s1_1 = 0.f, s2_1 = 0.f;
        #pragma unroll
        for (int j = 0; j < 4; j++) {
            const int c0 = nBlock + warpCol + j * 8 + 2 * qcol;
            s1_0 += acc[i][j][0] * a1x[j] + acc[i][j][1] * a1y[j];
            s2_0 += acc[i][j][0] * a2x[j] + acc[i][j][1] * a2y[j];
            s1_1 += acc[i][j][2] * a1x[j] + acc[i][j][3] * a1y[j];
            s2_1 += acc[i][j][2] * a2x[j] + acc[i][j][3] * a2y[j];
            if (r0 < M) {
                __half2 h = __floats2half2_rn(acc[i][j][0], acc[i][j][1]);
                *(__half2*)(Chalf + (size_t)r0 * 256 + c0) = h;
            }
            if (r1 < M) {
                __half2 h = __floats2half2_rn(acc[i][j][2], acc[i][j][3]);
                *(__half2*)(Chalf + (size_t)r1 * 256 + c0) = h;
            }
        }
        #pragma unroll
        for (int off = 1; off < 4; off <<= 1) {
            s1_0 += __shfl_xor_sync(0xffffffffu, s1_0, off);
            s2_0 += __shfl_xor_sync(0xffffffffu, s2_0, off);
            s1_1 += __shfl_xor_sync(0xffffffffu, s1_1, off);
            s2_1 += __shfl_xor_sync(0xffffffffu, s2_1, off);
        }
        if (qcol == 0) {
            if (r0 < M) {
                atomicAdd(&g_ssrc[r0], s1_0);
                atomicAdd(&g_sdst[r0], s2_0);
            }
            if (r1 < M) {
                atomicAdd(&g_ssrc[r1], s1_1);
                atomicAdd(&g_sdst[r1], s2_1);
            }
        }
    }
}

// ---------------- edge aggregation: one warp per node, fp16 gather -----------
__device__ __forceinline__ float elu1(float x) {
    return x > 0.f ? x : (__expf(x) - 1.f);
}

__global__ __launch_bounds__(256) void agg_k(const __half* __restrict__ h2h,
                                             float* __restrict__ out, int n) {
    int warp = (blockIdx.x * blockDim.x + threadIdx.x) >> 5;
    int lane = threadIdx.x & 31;
    if (warp >= n) return;
    const int start = g_rowptr[warp];
    const int end   = g_rowptr[warp + 1];
    const float s_i = g_ssrc[warp];

    float acc[8];
    #pragma unroll
    for (int t = 0; t < 8; t++) acc[t] = 0.f;
    float denom = 0.f;

    for (int j = start; j < end; j += 32) {
        int myj = j + lane;
        float e = 0.f;
        int d = 0;
        if (myj < end) {
            d = g_col[myj];
            float sc = s_i + g_sdst[d];
            float l  = sc > 0.f ? sc : 0.2f * sc;
            e = __expf(-l);
        }
        int cnt = end - j;
        if (cnt > 32) cnt = 32;
        #pragma unroll 4
        for (int k = 0; k < cnt; k++) {
            float ek = __shfl_sync(0xffffffffu, e, k);
            int   dk = __shfl_sync(0xffffffffu, d, k);
            uint4 v = ((const uint4*)(h2h + (size_t)dk * 256))[lane];
            float2 f0 = __half22float2(*(__half2*)&v.x);
            float2 f1 = __half22float2(*(__half2*)&v.y);
            float2 f2 = __half22float2(*(__half2*)&v.z);
            float2 f3 = __half22float2(*(__half2*)&v.w);
            acc[0] += ek * f0.x; acc[1] += ek * f0.y;
            acc[2] += ek * f1.x; acc[3] += ek * f1.y;
            acc[4] += ek * f2.x; acc[5] += ek * f2.y;
            acc[6] += ek * f3.x; acc[7] += ek * f3.y;
            denom += ek;
        }
    }
    float inv = denom > 0.f ? 1.0f / denom : 0.f;
    float o[8];
    #pragma unroll
    for (int t = 0; t < 8; t++) o[t] = elu1(acc[t] * inv);
    float4* orow = (float4*)(out + (size_t)warp * 256 + lane * 8);
    orow[0] = *(float4*)&o[0];
    orow[1] = *(float4*)&o[4];
}

// ---------------- launch -----------------------------------------------------
extern "C" void kernel_launch(void* const* d_in, const int* in_sizes, int n_in,
                              void* d_out, int out_size) {
    const float* emb  = (const float*)d_in[0];
    const float* W1   = (const float*)d_in[1];
    const float* a1   = (const float*)d_in[2];
    const float* W2   = (const float*)d_in[3];
    const float* a2   = (const float*)d_in[4];
    const int*   edges = (const int*)d_in[5];

    const int N = in_sizes[0] / DDIM;     // 100000
    const int E = in_sizes[5] / 2;        // 3300000
    const int* src = edges;
    const int* dst = edges + E;

    __half* h2h;  cudaGetSymbolAddress((void**)&h2h,  g_h2h);
    float*  hmid; cudaGetSymbolAddress((void**)&hmid, g_hmid);
    __nv_bfloat16 *w1h, *w1l, *w2h, *w2l;
    cudaGetSymbolAddress((void**)&w1h, g_W1h);
    cudaGetSymbolAddress((void**)&w1l, g_W1l);
    cudaGetSymbolAddress((void**)&w2h, g_W2h);
    cudaGetSymbolAddress((void**)&w2l, g_W2l);
    float* out = (float*)d_out;

    cudaFuncSetAttribute(mmagemm_k, cudaFuncAttributeMaxDynamicSharedMemorySize, GSMEM_B);

    const int TB = 256;
    dim3 gemm_grid((N + 127) / 128, 2);

    // W prep + CSR build
    wsplit_k<<<256, 256>>>(W1, w1h, w1l);
    wsplit_k<<<256, 256>>>(W2, w2h, w2l);
    zero_counts_k<<<(N + TB - 1) / TB, TB>>>(N);
    hist_k<<<(E + TB - 1) / TB, TB>>>(src, E);
    scan_k<<<1, 1024>>>(N);
    scatter_k<<<(E + TB - 1) / TB, TB>>>(src, dst, E);

    // layer 1
    zero_s_k<<<(N + TB - 1) / TB, TB>>>(N);
    mmagemm_k<<<gemm_grid, TB, GSMEM_B>>>(emb, w1h, w1l, a1, h2h, N);
    agg_k<<<(N * 32 + TB - 1) / TB, TB>>>(h2h, hmid, N);

    // layer 2
    zero_s_k<<<(N + TB - 1) / TB, TB>>>(N);
    mmagemm_k<<<gemm_grid, TB, GSMEM_B>>>(hmid, w2h, w2l, a2, h2h, N);
    agg_k<<<(N * 32 + TB - 1) / TB, TB>>>(h2h, out, N);
}

// round 7
// speedup vs baseline: 2.0574x; 1.0941x over previous
#include <cuda_runtime.h>
#include <cuda_fp16.h>
#include <cuda_bf16.h>
#include <cstdint>

#define NNODE 100000
#define DDIM  256
#define EMAX  3400000

// ---------------- scratch (static device globals; no allocation) -------------
__device__ __half g_h2h [(size_t)NNODE * DDIM];   // h @ W (fp16, for gather)
__device__ float  g_hmid[(size_t)NNODE * DDIM];   // output of layer 1
__device__ float  g_ssrc[NNODE];
__device__ float  g_sdst[NNODE];
__device__ int    g_counts[NNODE];
__device__ int    g_rowptr[NNODE + 1];
__device__ int    g_cursor[NNODE];
__device__ int    g_col[EMAX];
// W^T split into bf16 hi/lo, per layer: [N=256][K=256]
__device__ __nv_bfloat16 g_W1h[65536], g_W1l[65536];
__device__ __nv_bfloat16 g_W2h[65536], g_W2l[65536];

// ---------------- helpers -----------------------------------------------------
__device__ __forceinline__ uint32_t smem_u32(const void* p) {
    uint32_t a;
    asm("{ .reg .u64 t; cvta.to.shared.u64 t, %1; cvt.u32.u64 %0, t; }" : "=r"(a) : "l"(p));
    return a;
}
__device__ __forceinline__ void cpasync16(uint32_t dst, const void* src) {
    asm volatile("cp.async.cg.shared.global [%0], [%1], 16;" :: "r"(dst), "l"(src));
}
#define CP_COMMIT() asm volatile("cp.async.commit_group;")
#define CP_WAIT0()  asm volatile("cp.async.wait_group 0;")
#define LDSM4(R, addr) \
    asm volatile("ldmatrix.sync.aligned.m8n8.x4.shared.b16 {%0,%1,%2,%3}, [%4];" \
                 : "=r"((R)[0]), "=r"((R)[1]), "=r"((R)[2]), "=r"((R)[3]) : "r"(addr))

__device__ __forceinline__ void mma_bf16(float* c, const uint32_t* a,
                                         uint32_t b0, uint32_t b1) {
    asm volatile(
        "mma.sync.aligned.m16n8k16.row.col.f32.bf16.bf16.f32 "
        "{%0,%1,%2,%3}, {%4,%5,%6,%7}, {%8,%9}, {%0,%1,%2,%3};"
        : "+f"(c[0]), "+f"(c[1]), "+f"(c[2]), "+f"(c[3])
        : "r"(a[0]), "r"(a[1]), "r"(a[2]), "r"(a[3]), "r"(b0), "r"(b1));
}

// ---------------- CSR build --------------------------------------------------
__global__ void zero_counts_k(int n) {
    int i = blockIdx.x * blockDim.x + threadIdx.x;
    if (i < n) g_counts[i] = 0;
}

__global__ void zero_s_k(int n) {
    int i = blockIdx.x * blockDim.x + threadIdx.x;
    if (i < n) { g_ssrc[i] = 0.f; g_sdst[i] = 0.f; }
}

__global__ void hist_k(const int* __restrict__ src, int E) {
    int i = (blockIdx.x * blockDim.x + threadIdx.x) * 4;
    if (i + 3 < E) {
        int4 s = *(const int4*)(src + i);
        atomicAdd(&g_counts[s.x], 1);
        atomicAdd(&g_counts[s.y], 1);
        atomicAdd(&g_counts[s.z], 1);
        atomicAdd(&g_counts[s.w], 1);
    } else {
        for (int q = i; q < E; q++) atomicAdd(&g_counts[src[q]], 1);
    }
}

__global__ void scan_k(int n) {
    __shared__ int wsum[32];
    __shared__ int carry;
    const int tid = threadIdx.x, lane = tid & 31, w = tid >> 5;
    if (tid == 0) carry = 0;
    __syncthreads();
    for (int base = 0; base < n; base += 4096) {
        int i0 = base + tid * 4;
        int v0 = 0, v1 = 0, v2 = 0, v3 = 0;
        if (i0 + 3 < n) {
            int4 t = *(const int4*)&g_counts[i0];
            v0 = t.x; v1 = t.y; v2 = t.z; v3 = t.w;
        } else {
            if (i0 + 0 < n) v0 = g_counts[i0 + 0];
            if (i0 + 1 < n) v1 = g_counts[i0 + 1];
            if (i0 + 2 < n) v2 = g_counts[i0 + 2];
            if (i0 + 3 < n) v3 = g_counts[i0 + 3];
        }
        int s0 = v0, s1 = s0 + v1, s2 = s1 + v2, s3 = s2 + v3;
        int incl = s3;
        #pragma unroll
        for (int off = 1; off < 32; off <<= 1) {
            int u = __shfl_up_sync(0xffffffffu, incl, off);
            if (lane >= off) incl += u;
        }
        if (lane == 31) wsum[w] = incl;
        __syncthreads();
        if (w == 0) {
            int x = wsum[lane], xi = x;
            #pragma unroll
            for (int off = 1; off < 32; off <<= 1) {
                int u = __shfl_up_sync(0xffffffffu, xi, off);
                if (lane >= off) xi += u;
            }
            wsum[lane] = xi - x;
        }
        __syncthreads();
        int eb = carry + wsum[w] + (incl - s3);
        if (i0 + 0 < n) { g_rowptr[i0 + 0] = eb;      g_cursor[i0 + 0] = eb;      }
        if (i0 + 1 < n) { g_rowptr[i0 + 1] = eb + s0; g_cursor[i0 + 1] = eb + s0; }
        if (i0 + 2 < n) { g_rowptr[i0 + 2] = eb + s1; g_cursor[i0 + 2] = eb + s1; }
        if (i0 + 3 < n) { g_rowptr[i0 + 3] = eb + s2; g_cursor[i0 + 3] = eb + s2; }
        __syncthreads();
        if (tid == 1023) carry += wsum[31] + incl;
        __syncthreads();
    }
    if (tid == 0) g_rowptr[n] = carry;
}

__global__ void scatter_k(const int* __restrict__ src, const int* __restrict__ dst, int E) {
    int i = (blockIdx.x * blockDim.x + threadIdx.x) * 4;
    if (i + 3 < E) {
        int4 s = *(const int4*)(src + i);
        int4 d = *(const int4*)(dst + i);
        g_col[atomicAdd(&g_cursor[s.x], 1)] = d.x;
        g_col[atomicAdd(&g_cursor[s.y], 1)] = d.y;
        g_col[atomicAdd(&g_cursor[s.z], 1)] = d.z;
        g_col[atomicAdd(&g_cursor[s.w], 1)] = d.w;
    } else {
        for (int q = i; q < E; q++)
            g_col[atomicAdd(&g_cursor[src[q]], 1)] = dst[q];
    }
}

// ---------------- W transpose + bf16 hi/lo split ------------------------------
__global__ void wsplit_k(const float* __restrict__ W,
                         __nv_bfloat16* __restrict__ Wh,
                         __nv_bfloat16* __restrict__ Wl) {
    int n = blockIdx.x, k = threadIdx.x;
    float v = W[k * 256 + n];
    __nv_bfloat16 h = __float2bfloat16_rn(v);
    Wh[n * 256 + k] = h;
    Wl[n * 256 + k] = __float2bfloat16_rn(v - __bfloat162float(h));
}

// ---------------- HMMA split-precision GEMM v2 -------------------------------
// C[M,256] = A[M,256] @ W ; D = Ah*Bh + Ah*Bl + Al*Bh (bf16 hi/lo, fp32 acc).
// CTA 128x256, 8 warps (2m x 4n), warp tile 64x64, K chunk 32, double-buffered.
// B via cp.async; frags via ldmatrix.x4. Fused fp16 store + score projections.
#define STRIDE  80
#define A_L_OFF 10240
#define B_H_OFF 20480
#define B_L_OFF 40960
#define STAGE_B 61440
#define GSMEM_B (2 * STAGE_B)

__global__ __launch_bounds__(256, 1) void mmagemm_k(const float* __restrict__ A,
                                                    const __nv_bfloat16* __restrict__ Bh,
                                                    const __nv_bfloat16* __restrict__ Bl,
                                                    const float* __restrict__ avec,
                                                    __half* __restrict__ Chalf, int M) {
    extern __shared__ char smem[];
    const uint32_t sbase = smem_u32(smem);
    const int tid = threadIdx.x;
    const int rowBlock = blockIdx.x * 128;
    const int wid = tid >> 5, lane = tid & 31;
    const int warpRow = (wid >> 2) * 64;   // 0/64
    const int warpCol = (wid & 3) * 64;    // 0..192
    const int qrow = lane >> 2, qcol = lane & 3;

    float acc[4][8][4];
    #pragma unroll
    for (int i = 0; i < 4; i++)
        #pragma unroll
        for (int j = 0; j < 8; j++)
            #pragma unroll
            for (int t = 0; t < 4; t++) acc[i][j][t] = 0.f;

    // A producer mapping: thread t -> row t>>1, k-half t&1 (16 fp32)
    const int ldRow = tid >> 1, ldHalf = tid & 1;
    const int aRowG = rowBlock + ldRow;
    float fA[16];

    auto loadA = [&](int kc) {
        if (aRowG < M) {
            const float4* ap = (const float4*)(A + (size_t)aRowG * 256 + kc * 32 + ldHalf * 16);
            #pragma unroll
            for (int q = 0; q < 4; q++) *(float4*)&fA[q * 4] = ap[q];
        } else {
            #pragma unroll
            for (int q = 0; q < 16; q++) fA[q] = 0.f;
        }
    };
    auto storeA = [&](int s) {
        char* st = smem + s * STAGE_B;
        uint32_t hp[8], lp[8];
        #pragma unroll
        for (int j = 0; j < 8; j++) {
            float x0 = fA[2 * j], x1 = fA[2 * j + 1];
            __nv_bfloat16 h0 = __float2bfloat16_rn(x0);
            __nv_bfloat16 h1 = __float2bfloat16_rn(x1);
            __nv_bfloat162 hpp(h0, h1);
            hp[j] = *(uint32_t*)&hpp;
            __nv_bfloat16 l0 = __float2bfloat16_rn(x0 - __bfloat162float(h0));
            __nv_bfloat16 l1 = __float2bfloat16_rn(x1 - __bfloat162float(h1));
            __nv_bfloat162 lpp(l0, l1);
            lp[j] = *(uint32_t*)&lpp;
        }
        const int off = ldRow * STRIDE + ldHalf * 32;
        *(uint4*)(st + off)                = *(uint4*)&hp[0];
        *(uint4*)(st + off + 16)           = *(uint4*)&hp[4];
        *(uint4*)(st + A_L_OFF + off)      = *(uint4*)&lp[0];
        *(uint4*)(st + A_L_OFF + off + 16) = *(uint4*)&lp[4];
    };
    auto loadB = [&](int kc, int s) {
        const uint32_t sdst = sbase + s * STAGE_B + B_H_OFF;
        #pragma unroll
        for (int u = 0; u < 8; u++) {
            int idx = tid + u * 256;          // 0..2047
            int hl  = idx >> 10;              // 0: hi, 1: lo
            int rem = idx & 1023;
            int row = rem >> 2, q = rem & 3;
            const __nv_bfloat16* srcp = (hl ? Bl : Bh) + (size_t)row * 256 + kc * 32 + q * 8;
            cpasync16(sdst + hl * 20480 + row * STRIDE + q * 16, srcp);
        }
        CP_COMMIT();
    };

    // prologue
    loadA(0);
    loadB(0, 0);
    storeA(0);

    for (int kc = 0; kc < 8; kc++) {
        const int cur = kc & 1;
        CP_WAIT0();
        __syncthreads();
        if (kc < 7) { loadA(kc + 1); loadB(kc + 1, cur ^ 1); }

        const uint32_t sA = sbase + cur * STAGE_B;
        const uint32_t sB = sA + B_H_OFF;

        #pragma unroll
        for (int ks = 0; ks < 2; ks++) {
            uint32_t ah[4][4], al[4][4];
            const uint32_t arow = ((lane >> 3) & 1) * 8 + (lane & 7);
            const uint32_t akb  = ks * 32 + (lane >> 4) * 16;
            #pragma unroll
            for (int i = 0; i < 4; i++) {
                uint32_t addr = sA + (warpRow + i * 16 + arow) * STRIDE + akb;
                LDSM4(ah[i], addr);
                LDSM4(al[i], addr + A_L_OFF);
            }
            const uint32_t brow = (lane >> 4) * 8 + (lane & 7);
            const uint32_t bkb  = ks * 32 + ((lane >> 3) & 1) * 16;
            #pragma unroll
            for (int jj = 0; jj < 4; jj++) {
                uint32_t bh[4], bl[4];
                uint32_t addr = sB + (warpCol + jj * 16 + brow) * STRIDE + bkb;
                LDSM4(bh, addr);
                LDSM4(bl, addr + 20480);
                #pragma unroll
                for (int i = 0; i < 4; i++) {
                    mma_bf16(acc[i][jj * 2],     ah[i], bh[0], bh[1]);
                    mma_bf16(acc[i][jj * 2],     ah[i], bl[0], bl[1]);
                    mma_bf16(acc[i][jj * 2],     al[i], bh[0], bh[1]);
                    mma_bf16(acc[i][jj * 2 + 1], ah[i], bh[2], bh[3]);
                    mma_bf16(acc[i][jj * 2 + 1], ah[i], bl[2], bl[3]);
                    mma_bf16(acc[i][jj * 2 + 1], al[i], bh[2], bh[3]);
                }
            }
        }
        if (kc < 7) storeA(cur ^ 1);
    }

    // ---- epilogue: fp16 store + fused score projections ----
    float a1x[8], a1y[8], a2x[8], a2y[8];
    #pragma unroll
    for (int j = 0; j < 8; j++) {
        const int c0 = warpCol + j * 8 + 2 * qcol;
        float2 p1 = *(const float2*)(avec + c0);
        float2 p2 = *(const float2*)(avec + 256 + c0);
        a1x[j] = p1.x; a1y[j] = p1.y;
        a2x[j] = p2.x; a2y[j] = p2.y;
    }
    #pragma unroll
    for (int i = 0; i < 4; i++) {
        const int r0 = rowBlock + warpRow + i * 16 + qrow;
        const int r1 = r0 + 8;
        float s1_0 = 0.f, s2_0 = 0.f, s1_1 = 0.f, s2_1 = 0.f;
        #pragma unroll
        for (int j = 0; j < 8; j++) {
            const int c0 = warpCol + j * 8 + 2 * qcol;
            s1_0 += acc[i][j][0] * a1x[j] + acc[i][j][1] * a1y[j];
            s2_0 += acc[i][j][0] * a2x[j] + acc[i][j][1] * a2y[j];
            s1_1 += acc[i][j][2] * a1x[j] + acc[i][j][3] * a1y[j];
            s2_1 += acc[i][j][2] * a2x[j] + acc[i][j][3] * a2y[j];
            if (r0 < M) {
                __half2 h = __floats2half2_rn(acc[i][j][0], acc[i][j][1]);
                *(__half2*)(Chalf + (size_t)r0 * 256 + c0) = h;
            }
            if (r1 < M) {
                __half2 h = __floats2half2_rn(acc[i][j][2], acc[i][j][3]);
                *(__half2*)(Chalf + (size_t)r1 * 256 + c0) = h;
            }
        }
        #pragma unroll
        for (int off = 1; off < 4; off <<= 1) {
            s1_0 += __shfl_xor_sync(0xffffffffu, s1_0, off);
            s2_0 += __shfl_xor_sync(0xffffffffu, s2_0, off);
            s1_1 += __shfl_xor_sync(0xffffffffu, s1_1, off);
            s2_1 += __shfl_xor_sync(0xffffffffu, s2_1, off);
        }
        if (qcol == 0) {
            if (r0 < M) {
                atomicAdd(&g_ssrc[r0], s1_0);
                atomicAdd(&g_sdst[r0], s2_0);
            }
            if (r1 < M) {
                atomicAdd(&g_ssrc[r1], s1_1);
                atomicAdd(&g_sdst[r1], s2_1);
            }
        }
    }
}

// ---------------- edge aggregation: one warp per node, fp16 gather -----------
__device__ __forceinline__ float elu1(float x) {
    return x > 0.f ? x : (__expf(x) - 1.f);
}

__global__ __launch_bounds__(256) void agg_k(const __half* __restrict__ h2h,
                                             float* __restrict__ out, int n) {
    int warp = (blockIdx.x * blockDim.x + threadIdx.x) >> 5;
    int lane = threadIdx.x & 31;
    if (warp >= n) return;
    const int start = g_rowptr[warp];
    const int end   = g_rowptr[warp + 1];
    const float s_i = g_ssrc[warp];

    float acc[8];
    #pragma unroll
    for (int t = 0; t < 8; t++) acc[t] = 0.f;
    float denom = 0.f;

    for (int j = start; j < end; j += 32) {
        int myj = j + lane;
        float e = 0.f;
        int d = 0;
        if (myj < end) {
            d = g_col[myj];
            float sc = s_i + g_sdst[d];
            float l  = sc > 0.f ? sc : 0.2f * sc;
            e = __expf(-l);
        }
        int cnt = end - j;
        if (cnt > 32) cnt = 32;
        #pragma unroll 4
        for (int k = 0; k < cnt; k++) {
            float ek = __shfl_sync(0xffffffffu, e, k);
            int   dk = __shfl_sync(0xffffffffu, d, k);
            uint4 v = ((const uint4*)(h2h + (size_t)dk * 256))[lane];
            float2 f0 = __half22float2(*(__half2*)&v.x);
            float2 f1 = __half22float2(*(__half2*)&v.y);
            float2 f2 = __half22float2(*(__half2*)&v.z);
            float2 f3 = __half22float2(*(__half2*)&v.w);
            acc[0] += ek * f0.x; acc[1] += ek * f0.y;
            acc[2] += ek * f1.x; acc[3] += ek * f1.y;
            acc[4] += ek * f2.x; acc[5] += ek * f2.y;
            acc[6] += ek * f3.x; acc[7] += ek * f3.y;
            denom += ek;
        }
    }
    float inv = denom > 0.f ? 1.0f / denom : 0.f;
    float o[8];
    #pragma unroll
    for (int t = 0; t < 8; t++) o[t] = elu1(acc[t] * inv);
    float4* orow = (float4*)(out + (size_t)warp * 256 + lane * 8);
    orow[0] = *(float4*)&o[0];
    orow[1] = *(float4*)&o[4];
}

// ---------------- launch -----------------------------------------------------
extern "C" void kernel_launch(void* const* d_in, const int* in_sizes, int n_in,
                              void* d_out, int out_size) {
    const float* emb  = (const float*)d_in[0];
    const float* W1   = (const float*)d_in[1];
    const float* a1   = (const float*)d_in[2];
    const float* W2   = (const float*)d_in[3];
    const float* a2   = (const float*)d_in[4];
    const int*   edges = (const int*)d_in[5];

    const int N = in_sizes[0] / DDIM;     // 100000
    const int E = in_sizes[5] / 2;        // 3300000
    const int* src = edges;
    const int* dst = edges + E;

    __half* h2h;  cudaGetSymbolAddress((void**)&h2h,  g_h2h);
    float*  hmid; cudaGetSymbolAddress((void**)&hmid, g_hmid);
    __nv_bfloat16 *w1h, *w1l, *w2h, *w2l;
    cudaGetSymbolAddress((void**)&w1h, g_W1h);
    cudaGetSymbolAddress((void**)&w1l, g_W1l);
    cudaGetSymbolAddress((void**)&w2h, g_W2h);
    cudaGetSymbolAddress((void**)&w2l, g_W2l);
    float* out = (float*)d_out;

    cudaFuncSetAttribute(mmagemm_k, cudaFuncAttributeMaxDynamicSharedMemorySize, GSMEM_B);

    const int TB = 256;
    const int gemm_grid = (N + 127) / 128;
    const int e4 = (E / 4 + TB - 1) / TB + 1;

    // W prep + CSR build
    wsplit_k<<<256, 256>>>(W1, w1h, w1l);
    wsplit_k<<<256, 256>>>(W2, w2h, w2l);
    zero_counts_k<<<(N + TB - 1) / TB, TB>>>(N);
    hist_k<<<e4, TB>>>(src, E);
    scan_k<<<1, 1024>>>(N);
    scatter_k<<<e4, TB>>>(src, dst, E);

    // layer 1
    zero_s_k<<<(N + TB - 1) / TB, TB>>>(N);
    mmagemm_k<<<gemm_grid, TB, GSMEM_B>>>(emb, w1h, w1l, a1, h2h, N);
    agg_k<<<(N * 32 + TB - 1) / TB, TB>>>(h2h, hmid, N);

    // layer 2
    zero_s_k<<<(N + TB - 1) / TB, TB>>>(N);
    mmagemm_k<<<gemm_grid, TB, GSMEM_B>>>(hmid, w2h, w2l, a2, h2h, N);
    agg_k<<<(N * 32 + TB - 1) / TB, TB>>>(h2h, out, N);
}

// round 8
// speedup vs baseline: 2.2141x; 1.0762x over previous
#include <cuda_runtime.h>
#include <cuda_fp16.h>
#include <cuda_bf16.h>
#include <cstdint>

#define NNODE 100000
#define DDIM  256
#define EMAX  3400000

// ---------------- scratch (static device globals; no allocation) -------------
__device__ __half g_h2h [(size_t)NNODE * DDIM];   // h @ W (fp16, for gather)
__device__ float  g_hmid[(size_t)NNODE * DDIM];   // output of layer 1
__device__ float  g_ssrc[NNODE];
__device__ float  g_sdst[NNODE];
__device__ int    g_counts[NNODE];
__device__ int    g_rowptr[NNODE + 1];
__device__ int    g_cursor[NNODE];
__device__ int    g_col[EMAX];
// W^T split into fp16 hi/lo, per layer: [N=256][K=256]
__device__ __half g_W1h[65536], g_W1l[65536];
__device__ __half g_W2h[65536], g_W2l[65536];

// ---------------- helpers -----------------------------------------------------
__device__ __forceinline__ uint32_t smem_u32(const void* p) {
    uint32_t a;
    asm("{ .reg .u64 t; cvta.to.shared.u64 t, %1; cvt.u32.u64 %0, t; }" : "=r"(a) : "l"(p));
    return a;
}
__device__ __forceinline__ void cpasync16(uint32_t dst, const void* src) {
    asm volatile("cp.async.cg.shared.global [%0], [%1], 16;" :: "r"(dst), "l"(src));
}
#define CP_COMMIT() asm volatile("cp.async.commit_group;")
#define CP_WAIT0()  asm volatile("cp.async.wait_group 0;")
#define LDSM4(R, addr) \
    asm volatile("ldmatrix.sync.aligned.m8n8.x4.shared.b16 {%0,%1,%2,%3}, [%4];" \
                 : "=r"((R)[0]), "=r"((R)[1]), "=r"((R)[2]), "=r"((R)[3]) : "r"(addr))

__device__ __forceinline__ void mma_f16(float* c, const uint32_t* a,
                                        uint32_t b0, uint32_t b1) {
    asm volatile(
        "mma.sync.aligned.m16n8k16.row.col.f32.f16.f16.f32 "
        "{%0,%1,%2,%3}, {%4,%5,%6,%7}, {%8,%9}, {%0,%1,%2,%3};"
        : "+f"(c[0]), "+f"(c[1]), "+f"(c[2]), "+f"(c[3])
        : "r"(a[0]), "r"(a[1]), "r"(a[2]), "r"(a[3]), "r"(b0), "r"(b1));
}

// ---------------- CSR build --------------------------------------------------
__global__ void zero_counts_k(int n) {
    int i = blockIdx.x * blockDim.x + threadIdx.x;
    if (i < n) g_counts[i] = 0;
}

__global__ void hist_k(const int* __restrict__ src, int E) {
    int i = (blockIdx.x * blockDim.x + threadIdx.x) * 4;
    if (i + 3 < E) {
        int4 s = *(const int4*)(src + i);
        atomicAdd(&g_counts[s.x], 1);
        atomicAdd(&g_counts[s.y], 1);
        atomicAdd(&g_counts[s.z], 1);
        atomicAdd(&g_counts[s.w], 1);
    } else {
        for (int q = i; q < E; q++) atomicAdd(&g_counts[src[q]], 1);
    }
}

__global__ void scan_k(int n) {
    __shared__ int wsum[32];
    __shared__ int carry;
    const int tid = threadIdx.x, lane = tid & 31, w = tid >> 5;
    if (tid == 0) carry = 0;
    __syncthreads();
    for (int base = 0; base < n; base += 4096) {
        int i0 = base + tid * 4;
        int v0 = 0, v1 = 0, v2 = 0, v3 = 0;
        if (i0 + 3 < n) {
            int4 t = *(const int4*)&g_counts[i0];
            v0 = t.x; v1 = t.y; v2 = t.z; v3 = t.w;
        } else {
            if (i0 + 0 < n) v0 = g_counts[i0 + 0];
            if (i0 + 1 < n) v1 = g_counts[i0 + 1];
            if (i0 + 2 < n) v2 = g_counts[i0 + 2];
            if (i0 + 3 < n) v3 = g_counts[i0 + 3];
        }
        int s0 = v0, s1 = s0 + v1, s2 = s1 + v2, s3 = s2 + v3;
        int incl = s3;
        #pragma unroll
        for (int off = 1; off < 32; off <<= 1) {
            int u = __shfl_up_sync(0xffffffffu, incl, off);
            if (lane >= off) incl += u;
        }
        if (lane == 31) wsum[w] = incl;
        __syncthreads();
        if (w == 0) {
            int x = wsum[lane], xi = x;
            #pragma unroll
            for (int off = 1; off < 32; off <<= 1) {
                int u = __shfl_up_sync(0xffffffffu, xi, off);
                if (lane >= off) xi += u;
            }
            wsum[lane] = xi - x;
        }
        __syncthreads();
        int eb = carry + wsum[w] + (incl - s3);
        if (i0 + 0 < n) { g_rowptr[i0 + 0] = eb;      g_cursor[i0 + 0] = eb;      }
        if (i0 + 1 < n) { g_rowptr[i0 + 1] = eb + s0; g_cursor[i0 + 1] = eb + s0; }
        if (i0 + 2 < n) { g_rowptr[i0 + 2] = eb + s1; g_cursor[i0 + 2] = eb + s1; }
        if (i0 + 3 < n) { g_rowptr[i0 + 3] = eb + s2; g_cursor[i0 + 3] = eb + s2; }
        __syncthreads();
        if (tid == 1023) carry += wsum[31] + incl;
        __syncthreads();
    }
    if (tid == 0) g_rowptr[n] = carry;
}

__global__ void scatter_k(const int* __restrict__ src, const int* __restrict__ dst, int E) {
    int i = (blockIdx.x * blockDim.x + threadIdx.x) * 4;
    if (i + 3 < E) {
        int4 s = *(const int4*)(src + i);
        int4 d = *(const int4*)(dst + i);
        g_col[atomicAdd(&g_cursor[s.x], 1)] = d.x;
        g_col[atomicAdd(&g_cursor[s.y], 1)] = d.y;
        g_col[atomicAdd(&g_cursor[s.z], 1)] = d.z;
        g_col[atomicAdd(&g_cursor[s.w], 1)] = d.w;
    } else {
        for (int q = i; q < E; q++)
            g_col[atomicAdd(&g_cursor[src[q]], 1)] = dst[q];
    }
}

// ---------------- W transpose + fp16 hi/lo split ------------------------------
__global__ void wsplit_k(const float* __restrict__ W,
                         __half* __restrict__ Wh, __half* __restrict__ Wl) {
    int n = blockIdx.x, k = threadIdx.x;
    float v = W[k * 256 + n];
    __half h = __float2half_rn(v);
    Wh[n * 256 + k] = h;
    Wl[n * 256 + k] = __float2half_rn(v - __half2float(h));
}

// ---------------- HMMA fp16-split GEMM v3 ------------------------------------
// C[M,256] = A[M,256] @ W ; C = Ah*(Bh + Bl), A fp16 (err 2^-12), B exact.
// CTA 128x256, 8 warps (2m x 4n), warp tile 64x64, K chunk 32, double-buffered.
// Epilogue: fp16 C store + score projections reduced in smem (no global atomics).
#define STRIDE  80
#define B_H_OFF 10240
#define B_L_OFF 30720
#define STAGE_B 51200
#define GSMEM_B (2 * STAGE_B)

__global__ __launch_bounds__(256, 1) void mmagemm_k(const float* __restrict__ A,
                                                    const __half* __restrict__ Bh,
                                                    const __half* __restrict__ Bl,
                                                    const float* __restrict__ avec,
                                                    __half* __restrict__ Chalf, int M) {
    extern __shared__ char smem[];
    const uint32_t sbase = smem_u32(smem);
    const int tid = threadIdx.x;
    const int rowBlock = blockIdx.x * 128;
    const int wid = tid >> 5, lane = tid & 31;
    const int warpRow = (wid >> 2) * 64;   // 0/64
    const int warpCol = (wid & 3) * 64;    // 0..192
    const int qrow = lane >> 2, qcol = lane & 3;

    float acc[4][8][4];
    #pragma unroll
    for (int i = 0; i < 4; i++)
        #pragma unroll
        for (int j = 0; j < 8; j++)
            #pragma unroll
            for (int t = 0; t < 4; t++) acc[i][j][t] = 0.f;

    const int ldRow = tid >> 1, ldHalf = tid & 1;
    const int aRowG = rowBlock + ldRow;
    float fA[16];

    auto loadA = [&](int kc) {
        if (aRowG < M) {
            const float4* ap = (const float4*)(A + (size_t)aRowG * 256 + kc * 32 + ldHalf * 16);
            #pragma unroll
            for (int q = 0; q < 4; q++) *(float4*)&fA[q * 4] = ap[q];
        } else {
            #pragma unroll
            for (int q = 0; q < 16; q++) fA[q] = 0.f;
        }
    };
    auto storeA = [&](int s) {
        char* st = smem + s * STAGE_B;
        uint32_t hp[8];
        #pragma unroll
        for (int j = 0; j < 8; j++) {
            __half2 h = __floats2half2_rn(fA[2 * j], fA[2 * j + 1]);
            hp[j] = *(uint32_t*)&h;
        }
        const int off = ldRow * STRIDE + ldHalf * 32;
        *(uint4*)(st + off)      = *(uint4*)&hp[0];
        *(uint4*)(st + off + 16) = *(uint4*)&hp[4];
    };
    auto loadB = [&](int kc, int s) {
        const uint32_t sdst = sbase + s * STAGE_B + B_H_OFF;
        #pragma unroll
        for (int u = 0; u < 8; u++) {
            int idx = tid + u * 256;          // 0..2047
            int hl  = idx >> 10;              // 0: hi, 1: lo
            int rem = idx & 1023;
            int row = rem >> 2, q = rem & 3;
            const __half* srcp = (hl ? Bl : Bh) + (size_t)row * 256 + kc * 32 + q * 8;
            cpasync16(sdst + hl * 20480 + row * STRIDE + q * 16, srcp);
        }
        CP_COMMIT();
    };

    // prologue
    loadA(0);
    loadB(0, 0);
    storeA(0);

    for (int kc = 0; kc < 8; kc++) {
        const int cur = kc & 1;
        CP_WAIT0();
        __syncthreads();
        if (kc < 7) { loadA(kc + 1); loadB(kc + 1, cur ^ 1); }

        const uint32_t sA = sbase + cur * STAGE_B;
        const uint32_t sB = sA + B_H_OFF;

        #pragma unroll
        for (int ks = 0; ks < 2; ks++) {
            uint32_t ah[4][4];
            const uint32_t arow = ((lane >> 3) & 1) * 8 + (lane & 7);
            const uint32_t akb  = ks * 32 + (lane >> 4) * 16;
            #pragma unroll
            for (int i = 0; i < 4; i++) {
                uint32_t addr = sA + (warpRow + i * 16 + arow) * STRIDE + akb;
                LDSM4(ah[i], addr);
            }
            const uint32_t brow = (lane >> 4) * 8 + (lane & 7);
            const uint32_t bkb  = ks * 32 + ((lane >> 3) & 1) * 16;
            #pragma unroll
            for (int jj = 0; jj < 4; jj++) {
                uint32_t bh[4], bl[4];
                uint32_t addr = sB + (warpCol + jj * 16 + brow) * STRIDE + bkb;
                LDSM4(bh, addr);
                LDSM4(bl, addr + 20480);
                #pragma unroll
                for (int i = 0; i < 4; i++) {
                    mma_f16(acc[i][jj * 2],     ah[i], bh[0], bh[1]);
                    mma_f16(acc[i][jj * 2],     ah[i], bl[0], bl[1]);
                    mma_f16(acc[i][jj * 2 + 1], ah[i], bh[2], bh[3]);
                    mma_f16(acc[i][jj * 2 + 1], ah[i], bl[2], bl[3]);
                }
            }
        }
        if (kc < 7) storeA(cur ^ 1);
    }

    // ---- epilogue: fp16 store + score projections via smem reduction ----
    __syncthreads();
    float* sS1 = (float*)smem;          // [128]
    float* sS2 = (float*)smem + 128;    // [128]
    if (tid < 128) { sS1[tid] = 0.f; sS2[tid] = 0.f; }
    __syncthreads();

    float a1x[8], a1y[8], a2x[8], a2y[8];
    #pragma unroll
    for (int j = 0; j < 8; j++) {
        const int c0 = warpCol + j * 8 + 2 * qcol;
        float2 p1 = *(const float2*)(avec + c0);
        float2 p2 = *(const float2*)(avec + 256 + c0);
        a1x[j] = p1.x; a1y[j] = p1.y;
        a2x[j] = p2.x; a2y[j] = p2.y;
    }
    #pragma unroll
    for (int i = 0; i < 4; i++) {
        const int lr0 = warpRow + i * 16 + qrow;
        const int lr1 = lr0 + 8;
        const int r0 = rowBlock + lr0, r1 = rowBlock + lr1;
        float s1_0 = 0.f, s2_0 = 0.f, s1_1 = 0.f, s2_1 = 0.f;
        #pragma unroll
        for (int j = 0; j < 8; j++) {
            const int c0 = warpCol + j * 8 + 2 * qcol;
            s1_0 += acc[i][j][0] * a1x[j] + acc[i][j][1] * a1y[j];
            s2_0 += acc[i][j][0] * a2x[j] + acc[i][j][1] * a2y[j];
            s1_1 += acc[i][j][2] * a1x[j] + acc[i][j][3] * a1y[j];
            s2_1 += acc[i][j][2] * a2x[j] + acc[i][j][3] * a2y[j];
            if (r0 < M) {
                __half2 h = __floats2half2_rn(acc[i][j][0], acc[i][j][1]);
                *(__half2*)(Chalf + (size_t)r0 * 256 + c0) = h;
            }
            if (r1 < M) {
                __half2 h = __floats2half2_rn(acc[i][j][2], acc[i][j][3]);
                *(__half2*)(Chalf + (size_t)r1 * 256 + c0) = h;
            }
        }
        #pragma unroll
        for (int off = 1; off < 4; off <<= 1) {
            s1_0 += __shfl_xor_sync(0xffffffffu, s1_0, off);
            s2_0 += __shfl_xor_sync(0xffffffffu, s2_0, off);
            s1_1 += __shfl_xor_sync(0xffffffffu, s1_1, off);
            s2_1 += __shfl_xor_sync(0xffffffffu, s2_1, off);
        }
        if (qcol == 0) {
            atomicAdd(&sS1[lr0], s1_0);
            atomicAdd(&sS2[lr0], s2_0);
            atomicAdd(&sS1[lr1], s1_1);
            atomicAdd(&sS2[lr1], s2_1);
        }
    }
    __syncthreads();
    if (tid < 128 && rowBlock + tid < M) {
        g_ssrc[rowBlock + tid] = sS1[tid];
        g_sdst[rowBlock + tid] = sS2[tid];
    }
}

// ---------------- edge aggregation: one warp per node, fp16 gather -----------
__device__ __forceinline__ float elu1(float x) {
    return x > 0.f ? x : (__expf(x) - 1.f);
}

__global__ __launch_bounds__(256) void agg_k(const __half* __restrict__ h2h,
                                             float* __restrict__ out, int n) {
    int warp = (blockIdx.x * blockDim.x + threadIdx.x) >> 5;
    int lane = threadIdx.x & 31;
    if (warp >= n) return;
    const int start = g_rowptr[warp];
    const int end   = g_rowptr[warp + 1];
    const float s_i = g_ssrc[warp];

    float acc[8];
    #pragma unroll
    for (int t = 0; t < 8; t++) acc[t] = 0.f;
    float denom = 0.f;

    for (int j = start; j < end; j += 32) {
        int myj = j + lane;
        float e = 0.f;
        int d = 0;
        if (myj < end) {
            d = g_col[myj];
            float sc = s_i + g_sdst[d];
            float l  = sc > 0.f ? sc : 0.2f * sc;
            e = __expf(-l);
        }
        int cnt = end - j;
        if (cnt > 32) cnt = 32;
        #pragma unroll 4
        for (int k = 0; k < cnt; k++) {
            float ek = __shfl_sync(0xffffffffu, e, k);
            int   dk = __shfl_sync(0xffffffffu, d, k);
            uint4 v = ((const uint4*)(h2h + (size_t)dk * 256))[lane];
            float2 f0 = __half22float2(*(__half2*)&v.x);
            float2 f1 = __half22float2(*(__half2*)&v.y);
            float2 f2 = __half22float2(*(__half2*)&v.z);
            float2 f3 = __half22float2(*(__half2*)&v.w);
            acc[0] += ek * f0.x; acc[1] += ek * f0.y;
            acc[2] += ek * f1.x; acc[3] += ek * f1.y;
            acc[4] += ek * f2.x; acc[5] += ek * f2.y;
            acc[6] += ek * f3.x; acc[7] += ek * f3.y;
            denom += ek;
        }
    }
    float inv = denom > 0.f ? 1.0f / denom : 0.f;
    float o[8];
    #pragma unroll
    for (int t = 0; t < 8; t++) o[t] = elu1(acc[t] * inv);
    float4* orow = (float4*)(out + (size_t)warp * 256 + lane * 8);
    orow[0] = *(float4*)&o[0];
    orow[1] = *(float4*)&o[4];
}

// ---------------- launch -----------------------------------------------------
extern "C" void kernel_launch(void* const* d_in, const int* in_sizes, int n_in,
                              void* d_out, int out_size) {
    const float* emb  = (const float*)d_in[0];
    const float* W1   = (const float*)d_in[1];
    const float* a1   = (const float*)d_in[2];
    const float* W2   = (const float*)d_in[3];
    const float* a2   = (const float*)d_in[4];
    const int*   edges = (const int*)d_in[5];

    const int N = in_sizes[0] / DDIM;     // 100000
    const int E = in_sizes[5] / 2;        // 3300000
    const int* src = edges;
    const int* dst = edges + E;

    __half* h2h;  cudaGetSymbolAddress((void**)&h2h,  g_h2h);
    float*  hmid; cudaGetSymbolAddress((void**)&hmid, g_hmid);
    __half *w1h, *w1l, *w2h, *w2l;
    cudaGetSymbolAddress((void**)&w1h, g_W1h);
    cudaGetSymbolAddress((void**)&w1l, g_W1l);
    cudaGetSymbolAddress((void**)&w2h, g_W2h);
    cudaGetSymbolAddress((void**)&w2l, g_W2l);
    float* out = (float*)d_out;

    cudaFuncSetAttribute(mmagemm_k, cudaFuncAttributeMaxDynamicSharedMemorySize, GSMEM_B);

    const int TB = 256;
    const int gemm_grid = (N + 127) / 128;
    const int e4 = (E / 4 + TB - 1) / TB + 1;

    // W prep + CSR build
    wsplit_k<<<256, 256>>>(W1, w1h, w1l);
    wsplit_k<<<256, 256>>>(W2, w2h, w2l);
    zero_counts_k<<<(N + TB - 1) / TB, TB>>>(N);
    hist_k<<<e4, TB>>>(src, E);
    scan_k<<<1, 1024>>>(N);
    scatter_k<<<e4, TB>>>(src, dst, E);

    // layer 1
    mmagemm_k<<<gemm_grid, TB, GSMEM_B>>>(emb, w1h, w1l, a1, h2h, N);
    agg_k<<<(N * 32 + TB - 1) / TB, TB>>>(h2h, hmid, N);

    // layer 2
    mmagemm_k<<<gemm_grid, TB, GSMEM_B>>>(hmid, w2h, w2l, a2, h2h, N);
    agg_k<<<(N * 32 + TB - 1) / TB, TB>>>(h2h, out, N);
}

// round 9
// speedup vs baseline: 2.5647x; 1.1583x over previous
#include <cuda_runtime.h>
#include <cuda_fp16.h>
#include <cuda_bf16.h>
#include <cstdint>

#define NNODE 100000
#define DDIM  256
#define EMAX  3400000

// ---------------- scratch (static device globals; no allocation) -------------
__device__ __half g_h2h  [(size_t)NNODE * DDIM];  // h @ W (fp16, gather source)
__device__ __half g_hmidh[(size_t)NNODE * DDIM];  // layer-1 output (fp16)
__device__ float  g_ssrc[NNODE];
__device__ float  g_sdst[NNODE];
__device__ int    g_counts[NNODE];
__device__ int    g_rowptr[NNODE + 1];
__device__ int    g_cursor[NNODE];
__device__ int    g_col[EMAX];
__device__ int    g_bsum[64];
__device__ int    g_boff[64];
// W^T split into fp16 hi/lo, per layer: [N=256][K=256]
__device__ __half g_W1h[65536], g_W1l[65536];
__device__ __half g_W2h[65536], g_W2l[65536];

// ---------------- helpers -----------------------------------------------------
__device__ __forceinline__ uint32_t smem_u32(const void* p) {
    uint32_t a;
    asm("{ .reg .u64 t; cvta.to.shared.u64 t, %1; cvt.u32.u64 %0, t; }" : "=r"(a) : "l"(p));
    return a;
}
__device__ __forceinline__ void cpasync16(uint32_t dst, const void* src) {
    asm volatile("cp.async.cg.shared.global [%0], [%1], 16;" :: "r"(dst), "l"(src));
}
#define CP_COMMIT() asm volatile("cp.async.commit_group;")
#define CP_WAIT0()  asm volatile("cp.async.wait_group 0;")
#define LDSM4(R, addr) \
    asm volatile("ldmatrix.sync.aligned.m8n8.x4.shared.b16 {%0,%1,%2,%3}, [%4];" \
                 : "=r"((R)[0]), "=r"((R)[1]), "=r"((R)[2]), "=r"((R)[3]) : "r"(addr))

__device__ __forceinline__ void mma_f16(float* c, const uint32_t* a,
                                        uint32_t b0, uint32_t b1) {
    asm volatile(
        "mma.sync.aligned.m16n8k16.row.col.f32.f16.f16.f32 "
        "{%0,%1,%2,%3}, {%4,%5,%6,%7}, {%8,%9}, {%0,%1,%2,%3};"
        : "+f"(c[0]), "+f"(c[1]), "+f"(c[2]), "+f"(c[3])
        : "r"(a[0]), "r"(a[1]), "r"(a[2]), "r"(a[3]), "r"(b0), "r"(b1));
}

// ---------------- CSR build --------------------------------------------------
__global__ void zero_counts_k(int n) {
    int i = blockIdx.x * blockDim.x + threadIdx.x;
    if (i < n) g_counts[i] = 0;
}

__global__ void hist_k(const int* __restrict__ src, int E) {
    int i = (blockIdx.x * blockDim.x + threadIdx.x) * 4;
    if (i + 3 < E) {
        int4 s = *(const int4*)(src + i);
        atomicAdd(&g_counts[s.x], 1);
        atomicAdd(&g_counts[s.y], 1);
        atomicAdd(&g_counts[s.z], 1);
        atomicAdd(&g_counts[s.w], 1);
    } else {
        for (int q = i; q < E; q++) atomicAdd(&g_counts[src[q]], 1);
    }
}

// phase 1: per-block (4096 elems) exclusive scan into rowptr + block sums
__global__ void scan1_k(int n) {
    __shared__ int wsum[32];
    const int tid = threadIdx.x, lane = tid & 31, w = tid >> 5;
    const int i0 = blockIdx.x * 4096 + tid * 4;
    int v0 = 0, v1 = 0, v2 = 0, v3 = 0;
    if (i0 + 3 < n) {
        int4 t = *(const int4*)&g_counts[i0];
        v0 = t.x; v1 = t.y; v2 = t.z; v3 = t.w;
    } else {
        if (i0 + 0 < n) v0 = g_counts[i0 + 0];
        if (i0 + 1 < n) v1 = g_counts[i0 + 1];
        if (i0 + 2 < n) v2 = g_counts[i0 + 2];
        if (i0 + 3 < n) v3 = g_counts[i0 + 3];
    }
    int s0 = v0, s1 = s0 + v1, s2 = s1 + v2, s3 = s2 + v3;
    int incl = s3;
    #pragma unroll
    for (int off = 1; off < 32; off <<= 1) {
        int u = __shfl_up_sync(0xffffffffu, incl, off);
        if (lane >= off) incl += u;
    }
    if (lane == 31) wsum[w] = incl;
    __syncthreads();
    if (w == 0) {
        int x = wsum[lane], xi = x;
        #pragma unroll
        for (int off = 1; off < 32; off <<= 1) {
            int u = __shfl_up_sync(0xffffffffu, xi, off);
            if (lane >= off) xi += u;
        }
        if (lane == 31) g_bsum[blockIdx.x] = xi;   // block total
        wsum[lane] = xi - x;                        // exclusive warp offset
    }
    __syncthreads();
    int eb = wsum[w] + (incl - s3);
    if (i0 + 0 < n) g_rowptr[i0 + 0] = eb;
    if (i0 + 1 < n) g_rowptr[i0 + 1] = eb + s0;
    if (i0 + 2 < n) g_rowptr[i0 + 2] = eb + s1;
    if (i0 + 3 < n) g_rowptr[i0 + 3] = eb + s2;
}

// phase 2: scan the block sums (1 warp)
__global__ void scan2_k(int nb, int n) {
    int lane = threadIdx.x;
    int v = (lane < nb) ? g_bsum[lane] : 0;
    int xi = v;
    #pragma unroll
    for (int off = 1; off < 32; off <<= 1) {
        int u = __shfl_up_sync(0xffffffffu, xi, off);
        if (lane >= off) xi += u;
    }
    if (lane < nb) g_boff[lane] = xi - v;
    if (lane == 31) g_rowptr[n] = xi;   // grand total
}

// phase 3: add block offsets, fill cursor
__global__ void scan3_k(int n) {
    const int i0 = blockIdx.x * 4096 + threadIdx.x * 4;
    const int off = g_boff[blockIdx.x];
    #pragma unroll
    for (int q = 0; q < 4; q++) {
        int i = i0 + q;
        if (i < n) {
            int v = g_rowptr[i] + off;
            g_rowptr[i] = v;
            g_cursor[i] = v;
        }
    }
}

__global__ void scatter_k(const int* __restrict__ src, const int* __restrict__ dst, int E) {
    int i = (blockIdx.x * blockDim.x + threadIdx.x) * 4;
    if (i + 3 < E) {
        int4 s = *(const int4*)(src + i);
        int4 d = *(const int4*)(dst + i);
        g_col[atomicAdd(&g_cursor[s.x], 1)] = d.x;
        g_col[atomicAdd(&g_cursor[s.y], 1)] = d.y;
        g_col[atomicAdd(&g_cursor[s.z], 1)] = d.z;
        g_col[atomicAdd(&g_cursor[s.w], 1)] = d.w;
    } else {
        for (int q = i; q < E; q++)
            g_col[atomicAdd(&g_cursor[src[q]], 1)] = dst[q];
    }
}

// ---------------- W transpose + fp16 hi/lo split ------------------------------
__global__ void wsplit_k(const float* __restrict__ W,
                         __half* __restrict__ Wh, __half* __restrict__ Wl) {
    int n = blockIdx.x, k = threadIdx.x;
    float v = W[k * 256 + n];
    __half h = __float2half_rn(v);
    Wh[n * 256 + k] = h;
    Wl[n * 256 + k] = __float2half_rn(v - __half2float(h));
}

// ---------------- HMMA fp16-split GEMM ---------------------------------------
// C[M,256] = A[M,256] @ W ; C = Ah*(Bh + Bl); A fp16 (input fp32 or fp16).
// CTA 128x256, 8 warps (2m x 4n), warp tile 64x64, K chunk 32, double-buffered.
#define STRIDE  80
#define B_H_OFF 10240
#define STAGE_B 51200
#define GSMEM_B (2 * STAGE_B)

template <int AF32>
__global__ __launch_bounds__(256, 1) void mmagemm_k(const void* __restrict__ Av,
                                                    const __half* __restrict__ Bh,
                                                    const __half* __restrict__ Bl,
                                                    const float* __restrict__ avec,
                                                    __half* __restrict__ Chalf, int M) {
    extern __shared__ char smem[];
    const uint32_t sbase = smem_u32(smem);
    const int tid = threadIdx.x;
    const int rowBlock = blockIdx.x * 128;
    const int wid = tid >> 5, lane = tid & 31;
    const int warpRow = (wid >> 2) * 64;
    const int warpCol = (wid & 3) * 64;
    const int qrow = lane >> 2, qcol = lane & 3;

    float acc[4][8][4];
    #pragma unroll
    for (int i = 0; i < 4; i++)
        #pragma unroll
        for (int j = 0; j < 8; j++)
            #pragma unroll
            for (int t = 0; t < 4; t++) acc[i][j][t] = 0.f;

    const int ldRow = tid >> 1, ldHalf = tid & 1;
    const int aRowG = rowBlock + ldRow;
    float fA[16];

    auto loadA = [&](int kc) {
        if constexpr (AF32) {
            const float* A = (const float*)Av;
            if (aRowG < M) {
                const float4* ap = (const float4*)(A + (size_t)aRowG * 256 + kc * 32 + ldHalf * 16);
                #pragma unroll
                for (int q = 0; q < 4; q++) *(float4*)&fA[q * 4] = ap[q];
            } else {
                #pragma unroll
                for (int q = 0; q < 16; q++) fA[q] = 0.f;
            }
        }
    };
    auto storeA = [&](int s) {
        if constexpr (AF32) {
            char* st = smem + s * STAGE_B;
            uint32_t hp[8];
            #pragma unroll
            for (int j = 0; j < 8; j++) {
                __half2 h = __floats2half2_rn(fA[2 * j], fA[2 * j + 1]);
                hp[j] = *(uint32_t*)&h;
            }
            const int off = ldRow * STRIDE + ldHalf * 32;
            *(uint4*)(st + off)      = *(uint4*)&hp[0];
            *(uint4*)(st + off + 16) = *(uint4*)&hp[4];
        }
    };
    auto loadB = [&](int kc, int s) {
        const uint32_t sdst = sbase + s * STAGE_B + B_H_OFF;
        #pragma unroll
        for (int u = 0; u < 8; u++) {
            int idx = tid + u * 256;          // 0..2047
            int hl  = idx >> 10;              // 0: hi, 1: lo
            int rem = idx & 1023;
            int row = rem >> 2, q = rem & 3;
            const __half* srcp = (hl ? Bl : Bh) + (size_t)row * 256 + kc * 32 + q * 8;
            cpasync16(sdst + hl * 20480 + row * STRIDE + q * 16, srcp);
        }
        if constexpr (!AF32) {
            const __half* A = (const __half*)Av;
            const uint32_t adst = sbase + s * STAGE_B;
            #pragma unroll
            for (int u = 0; u < 2; u++) {
                int idx = tid + u * 256;      // 0..511
                int row = idx >> 2, q = idx & 3;
                int grow = rowBlock + row;
                const __half* srcp = A + (size_t)(grow < M ? grow : M - 1) * 256 + kc * 32 + q * 8;
                cpasync16(adst + row * STRIDE + q * 16, srcp);
            }
        }
        CP_COMMIT();
    };

    // prologue
    loadA(0);
    loadB(0, 0);
    storeA(0);

    for (int kc = 0; kc < 8; kc++) {
        const int cur = kc & 1;
        CP_WAIT0();
        __syncthreads();
        if (kc < 7) { loadA(kc + 1); loadB(kc + 1, cur ^ 1); }

        const uint32_t sA = sbase + cur * STAGE_B;
        const uint32_t sB = sA + B_H_OFF;

        #pragma unroll
        for (int ks = 0; ks < 2; ks++) {
            uint32_t ah[4][4];
            const uint32_t arow = ((lane >> 3) & 1) * 8 + (lane & 7);
            const uint32_t akb  = ks * 32 + (lane >> 4) * 16;
            #pragma unroll
            for (int i = 0; i < 4; i++) {
                uint32_t addr = sA + (warpRow + i * 16 + arow) * STRIDE + akb;
                LDSM4(ah[i], addr);
            }
            const uint32_t brow = (lane >> 4) * 8 + (lane & 7);
            const uint32_t bkb  = ks * 32 + ((lane >> 3) & 1) * 16;
            #pragma unroll
            for (int jj = 0; jj < 4; jj++) {
                uint32_t bh[4], bl[4];
                uint32_t addr = sB + (warpCol + jj * 16 + brow) * STRIDE + bkb;
                LDSM4(bh, addr);
                LDSM4(bl, addr + 20480);
                #pragma unroll
                for (int i = 0; i < 4; i++) {
                    mma_f16(acc[i][jj * 2],     ah[i], bh[0], bh[1]);
                    mma_f16(acc[i][jj * 2],     ah[i], bl[0], bl[1]);
                    mma_f16(acc[i][jj * 2 + 1], ah[i], bh[2], bh[3]);
                    mma_f16(acc[i][jj * 2 + 1], ah[i], bl[2], bl[3]);
                }
            }
        }
        if (kc < 7) storeA(cur ^ 1);
    }

    // ---- epilogue: fp16 store + score projections via smem reduction ----
    __syncthreads();
    float* sS1 = (float*)smem;          // [128]
    float* sS2 = (float*)smem + 128;    // [128]
    if (tid < 128) { sS1[tid] = 0.f; sS2[tid] = 0.f; }
    __syncthreads();

    float a1x[8], a1y[8], a2x[8], a2y[8];
    #pragma unroll
    for (int j = 0; j < 8; j++) {
        const int c0 = warpCol + j * 8 + 2 * qcol;
        float2 p1 = *(const float2*)(avec + c0);
        float2 p2 = *(const float2*)(avec + 256 + c0);
        a1x[j] = p1.x; a1y[j] = p1.y;
        a2x[j] = p2.x; a2y[j] = p2.y;
    }
    #pragma unroll
    for (int i = 0; i < 4; i++) {
        const int lr0 = warpRow + i * 16 + qrow;
        const int lr1 = lr0 + 8;
        const int r0 = rowBlock + lr0, r1 = rowBlock + lr1;
        float s1_0 = 0.f, s2_0 = 0.f, s1_1 = 0.f, s2_1 = 0.f;
        #pragma unroll
        for (int j = 0; j < 8; j++) {
            const int c0 = warpCol + j * 8 + 2 * qcol;
            s1_0 += acc[i][j][0] * a1x[j] + acc[i][j][1] * a1y[j];
            s2_0 += acc[i][j][0] * a2x[j] + acc[i][j][1] * a2y[j];
            s1_1 += acc[i][j][2] * a1x[j] + acc[i][j][3] * a1y[j];
            s2_1 += acc[i][j][2] * a2x[j] + acc[i][j][3] * a2y[j];
            if (r0 < M) {
                __half2 h = __floats2half2_rn(acc[i][j][0], acc[i][j][1]);
                *(__half2*)(Chalf + (size_t)r0 * 256 + c0) = h;
            }
            if (r1 < M) {
                __half2 h = __floats2half2_rn(acc[i][j][2], acc[i][j][3]);
                *(__half2*)(Chalf + (size_t)r1 * 256 + c0) = h;
            }
        }
        #pragma unroll
        for (int off = 1; off < 4; off <<= 1) {
            s1_0 += __shfl_xor_sync(0xffffffffu, s1_0, off);
            s2_0 += __shfl_xor_sync(0xffffffffu, s2_0, off);
            s1_1 += __shfl_xor_sync(0xffffffffu, s1_1, off);
            s2_1 += __shfl_xor_sync(0xffffffffu, s2_1, off);
        }
        if (qcol == 0) {
            atomicAdd(&sS1[lr0], s1_0);
            atomicAdd(&sS2[lr0], s2_0);
            atomicAdd(&sS1[lr1], s1_1);
            atomicAdd(&sS2[lr1], s2_1);
        }
    }
    __syncthreads();
    if (tid < 128 && rowBlock + tid < M) {
        g_ssrc[rowBlock + tid] = sS1[tid];
        g_sdst[rowBlock + tid] = sS2[tid];
    }
}

// ---------------- edge aggregation: one warp per node, fp16 gather -----------
__device__ __forceinline__ float elu1(float x) {
    return x > 0.f ? x : (__expf(x) - 1.f);
}

template <typename OT>
__global__ __launch_bounds__(256) void agg_k(const __half* __restrict__ h2h,
                                             OT* __restrict__ out, int n) {
    int warp = (blockIdx.x * blockDim.x + threadIdx.x) >> 5;
    int lane = threadIdx.x & 31;
    if (warp >= n) return;
    const int start = g_rowptr[warp];
    const int end   = g_rowptr[warp + 1];
    const float s_i = g_ssrc[warp];

    float acc[8];
    #pragma unroll
    for (int t = 0; t < 8; t++) acc[t] = 0.f;
    float denom = 0.f;

    for (int j = start; j < end; j += 32) {
        int myj = j + lane;
        float e = 0.f;
        int d = 0;
        if (myj < end) {
            d = g_col[myj];
            float sc = s_i + g_sdst[d];
            float l  = sc > 0.f ? sc : 0.2f * sc;
            e = __expf(-l);
        }
        int cnt = end - j;
        if (cnt > 32) cnt = 32;
        #pragma unroll 4
        for (int k = 0; k < cnt; k++) {
            float ek = __shfl_sync(0xffffffffu, e, k);
            int   dk = __shfl_sync(0xffffffffu, d, k);
            uint4 v = ((const uint4*)(h2h + (size_t)dk * 256))[lane];
            float2 f0 = __half22float2(*(__half2*)&v.x);
            float2 f1 = __half22float2(*(__half2*)&v.y);
            float2 f2 = __half22float2(*(__half2*)&v.z);
            float2 f3 = __half22float2(*(__half2*)&v.w);
            acc[0] += ek * f0.x; acc[1] += ek * f0.y;
            acc[2] += ek * f1.x; acc[3] += ek * f1.y;
            acc[4] += ek * f2.x; acc[5] += ek * f2.y;
            acc[6] += ek * f3.x; acc[7] += ek * f3.y;
            denom += ek;
        }
    }
    float inv = denom > 0.f ? 1.0f / denom : 0.f;
    float o[8];
    #pragma unroll
    for (int t = 0; t < 8; t++) o[t] = elu1(acc[t] * inv);
    if constexpr (sizeof(OT) == 2) {
        uint32_t hb[4];
        #pragma unroll
        for (int t = 0; t < 4; t++) {
            __half2 h = __floats2half2_rn(o[2 * t], o[2 * t + 1]);
            hb[t] = *(uint32_t*)&h;
        }
        *(uint4*)((__half*)out + (size_t)warp * 256 + lane * 8) = *(uint4*)hb;
    } else {
        float4* orow = (float4*)((float*)out + (size_t)warp * 256 + lane * 8);
        orow[0] = *(float4*)&o[0];
        orow[1] = *(float4*)&o[4];
    }
}

// ---------------- launch -----------------------------------------------------
extern "C" void kernel_launch(void* const* d_in, const int* in_sizes, int n_in,
                              void* d_out, int out_size) {
    const float* emb  = (const float*)d_in[0];
    const float* W1   = (const float*)d_in[1];
    const float* a1   = (const float*)d_in[2];
    const float* W2   = (const float*)d_in[3];
    const float* a2   = (const float*)d_in[4];
    const int*   edges = (const int*)d_in[5];

    const int N = in_sizes[0] / DDIM;     // 100000
    const int E = in_sizes[5] / 2;        // 3300000
    const int* src = edges;
    const int* dst = edges + E;

    __half* h2h;   cudaGetSymbolAddress((void**)&h2h,   g_h2h);
    __half* hmidh; cudaGetSymbolAddress((void**)&hmidh, g_hmidh);
    __half *w1h, *w1l, *w2h, *w2l;
    cudaGetSymbolAddress((void**)&w1h, g_W1h);
    cudaGetSymbolAddress((void**)&w1l, g_W1l);
    cudaGetSymbolAddress((void**)&w2h, g_W2h);
    cudaGetSymbolAddress((void**)&w2l, g_W2l);
    float* out = (float*)d_out;

    cudaFuncSetAttribute(mmagemm_k<1>, cudaFuncAttributeMaxDynamicSharedMemorySize, GSMEM_B);
    cudaFuncSetAttribute(mmagemm_k<0>, cudaFuncAttributeMaxDynamicSharedMemorySize, GSMEM_B);

    const int TB = 256;
    const int gemm_grid = (N + 127) / 128;
    const int e4 = (E / 4 + TB - 1) / TB + 1;
    const int nscan = (N + 4095) / 4096;

    // fork: CSR build on side stream, GEMM prep + GEMM1 on main stream
    cudaStream_t s2;
    cudaEvent_t evFork, evJoin;
    cudaStreamCreateWithFlags(&s2, cudaStreamNonBlocking);
    cudaEventCreateWithFlags(&evFork, cudaEventDisableTiming);
    cudaEventCreateWithFlags(&evJoin, cudaEventDisableTiming);

    cudaEventRecord(evFork, 0);
    cudaStreamWaitEvent(s2, evFork, 0);

    // side stream: CSR build
    zero_counts_k<<<(N + TB - 1) / TB, TB, 0, s2>>>(N);
    hist_k<<<e4, TB, 0, s2>>>(src, E);
    scan1_k<<<nscan, 1024, 0, s2>>>(N);
    scan2_k<<<1, 32, 0, s2>>>(nscan, N);
    scan3_k<<<nscan, 1024, 0, s2>>>(N);
    scatter_k<<<e4, TB, 0, s2>>>(src, dst, E);
    cudaEventRecord(evJoin, s2);

    // main stream: W prep + layer-1 GEMM (independent of CSR)
    wsplit_k<<<256, 256>>>(W1, w1h, w1l);
    wsplit_k<<<256, 256>>>(W2, w2h, w2l);
    mmagemm_k<1><<<gemm_grid, TB, GSMEM_B>>>(emb, w1h, w1l, a1, h2h, N);

    // join: aggregation needs CSR + GEMM1
    cudaStreamWaitEvent(0, evJoin, 0);
    agg_k<__half><<<(N * 32 + TB - 1) / TB, TB>>>(h2h, hmidh, N);

    // layer 2 (A already fp16)
    mmagemm_k<0><<<gemm_grid, TB, GSMEM_B>>>(hmidh, w2h, w2l, a2, h2h, N);
    agg_k<float><<<(N * 32 + TB - 1) / TB, TB>>>(h2h, out, N);
}